// round 9
// baseline (speedup 1.0000x reference)
#include <cuda_runtime.h>
#include <cstdint>

// ---------------- problem constants (fixed-shape problem) ----------------
constexpr int NN   = 10000;  // nodes
constexpr int F1   = 64;     // hidden feat
constexpr int COUT = 16;     // classes

// GEMM1 (mma.sync tf32) tiling: 8 warps x (16m x 64n), BK=16, double buffer
constexpr int BM    = 128;
constexpr int BK    = 16;
constexpr int SPLIT = 4;
constexpr int NCH   = NN / BK;   // 625 exact
constexpr int LDRAW = 20;        // padded raw-A k-stride (floats)

// ---------------- device scratch (no allocation; device-code refs only) --
__device__ __align__(16) float g_deg[NN];
__device__ __align__(16) float g_dinv[NN];
__device__ __align__(16) float g_bufA[(size_t)NN * F1];
__device__ __align__(16) float g_bufB[(size_t)NN * F1];
__device__ __align__(16) float g_part[(size_t)SPLIT * NN * F1];
__device__ __align__(16) float g_wfrag[(size_t)NCH * 2048];  // B fragments hi/lo

__device__ __forceinline__ int clampN(int v) {
    v = v < 0 ? 0 : v;
    return v < NN ? v : NN - 1;
}

// ---------------- PTX helpers ----------------
__device__ __forceinline__ uint32_t tf32_rna(float f) {
    uint32_t u;
    asm("cvt.rna.tf32.f32 %0, %1;" : "=r"(u) : "f"(f));
    return u;
}
__device__ __forceinline__ void tf32split(float a, uint32_t& hi, uint32_t& lo) {
    hi = tf32_rna(a);
    lo = tf32_rna(a - __uint_as_float(hi));
}
__device__ __forceinline__ void mma8(float* d, const uint32_t* a, const uint32_t* b) {
    asm volatile(
        "mma.sync.aligned.m16n8k8.row.col.f32.tf32.tf32.f32 "
        "{%0,%1,%2,%3},{%4,%5,%6,%7},{%8,%9},{%0,%1,%2,%3};"
        : "+f"(d[0]), "+f"(d[1]), "+f"(d[2]), "+f"(d[3])
        : "r"(a[0]), "r"(a[1]), "r"(a[2]), "r"(a[3]), "r"(b[0]), "r"(b[1]));
}
__device__ __forceinline__ void cp16(uint32_t dst, const void* src) {
    asm volatile("cp.async.cg.shared.global [%0], [%1], 16;" :: "r"(dst), "l"(src));
}

// ---------------- degree / norm ----------------
__global__ void deg_init_kernel() {
    int i = blockIdx.x * blockDim.x + threadIdx.x;
    if (i < NN) g_deg[i] = 1.0f;
}
__global__ void deg_count_kernel(const int* __restrict__ ei, int E) {
    int e = blockIdx.x * blockDim.x + threadIdx.x;
    if (e < E) atomicAdd(&g_deg[clampN(ei[E + e])], 1.0f);
}
__global__ void dinv_kernel() {
    int i = blockIdx.x * blockDim.x + threadIdx.x;
    if (i < NN) g_dinv[i] = rsqrtf(g_deg[i]);
}

// ---------------- W1 -> fragment-order hi/lo (g_wfrag) [verified r8] ------
__global__ void wfrag_kernel(const float* __restrict__ W) {
    int idx = blockIdx.x * blockDim.x + threadIdx.x;
    if (idx >= NCH * 512) return;
    const int lane = idx & 31;
    const int n8   = (idx >> 5) & 7;
    const int k8   = (idx >> 8) & 1;
    const int c    = idx >> 9;
    const int g = lane >> 2, t = lane & 3;
    const int n  = n8 * 8 + g;
    const int k0 = c * 16 + k8 * 8 + t;
    const float w0 = W[(size_t)k0 * 64 + n];
    const float w1 = W[(size_t)(k0 + 4) * 64 + n];
    uint32_t h0, l0, h1, l1;
    tf32split(w0, h0, l0);
    tf32split(w1, h1, l1);
    float4 v = make_float4(__uint_as_float(h0), __uint_as_float(h1),
                           __uint_as_float(l0), __uint_as_float(l1));
    reinterpret_cast<float4*>(g_wfrag)[idx] = v;
}

// ---------------- GEMM1: mma.sync tf32 hi/lo, 8-warp strips, split-K ------
__global__ void __launch_bounds__(256, 2) gemm1_mma_kernel(const float* __restrict__ A) {
    __shared__ __align__(16) float rawA[2][BM][LDRAW];   // 20480 B
    __shared__ __align__(16) float bfrag[2][2048];       // 16384 B

    const int tid  = threadIdx.x;
    const int lane = tid & 31;
    const int wid  = tid >> 5;         // 0..7: owns rows [wid*16, wid*16+16)
    const int g    = lane >> 2;
    const int t    = lane & 3;
    const int m0   = blockIdx.x * BM;
    const int part = blockIdx.y;

    const int q = NCH / SPLIT, r = NCH % SPLIT;
    const int cBeg = part * q + (part < r ? part : r);
    const int nCh  = q + (part < r ? 1 : 0);

    // loader mapping: 512 A cp16 tasks + 512 B cp16 tasks; 2+2 per thread
    const int am0 = tid >> 2,         aj0 = (tid & 3) * 4;
    const int am1 = (tid + 256) >> 2, aj1 = ((tid + 256) & 3) * 4;
    const float* Ap0 = A + (size_t)clampN(m0 + am0) * NN + aj0;
    const float* Ap1 = A + (size_t)clampN(m0 + am1) * NN + aj1;

    const uint32_t aDst0 = (uint32_t)__cvta_generic_to_shared(&rawA[0][am0][aj0]);
    const uint32_t aDst1 = (uint32_t)__cvta_generic_to_shared(&rawA[0][am1][aj1]);
    const uint32_t bDst  = (uint32_t)__cvta_generic_to_shared(&bfrag[0][0]);
    const uint32_t RAW_STG_B = (uint32_t)(BM * LDRAW * 4);
    const uint32_t BF_STG_B  = (uint32_t)(2048 * 4);

    float acc[8][4] = {};   // [n8][reg]

    // prologue: chunk cBeg -> stage 0
    {
        const size_t kf = (size_t)cBeg * BK;
        cp16(aDst0, Ap0 + kf);
        cp16(aDst1, Ap1 + kf);
        const float* bsrc = &g_wfrag[(size_t)cBeg * 2048];
        cp16(bDst + (uint32_t)tid * 16,         bsrc + tid * 4);
        cp16(bDst + (uint32_t)(tid + 256) * 16, bsrc + (tid + 256) * 4);
        asm volatile("cp.async.commit_group;");
    }

    for (int i = 0; i < nCh; ++i) {
        const int s = i & 1;
        if (i + 1 < nCh) {
            const uint32_t ns = (uint32_t)(s ^ 1);
            const size_t kf = (size_t)(cBeg + i + 1) * BK;
            cp16(aDst0 + ns * RAW_STG_B, Ap0 + kf);
            cp16(aDst1 + ns * RAW_STG_B, Ap1 + kf);
            const float* bsrc = &g_wfrag[(size_t)(cBeg + i + 1) * 2048];
            cp16(bDst + ns * BF_STG_B + (uint32_t)tid * 16,         bsrc + tid * 4);
            cp16(bDst + ns * BF_STG_B + (uint32_t)(tid + 256) * 16, bsrc + (tid + 256) * 4);
            asm volatile("cp.async.commit_group;");
            asm volatile("cp.async.wait_group 1;");
        } else {
            asm volatile("cp.async.wait_group 0;");
        }
        __syncthreads();

        const float (*raw)[LDRAW] = rawA[s];
        const float4* bF = reinterpret_cast<const float4*>(&bfrag[s][0]);
        const int m = wid * 16 + g;

        #pragma unroll
        for (int k8 = 0; k8 < 2; ++k8) {
            const int c0 = k8 * 8 + t;
            const int c1 = c0 + 4;
            // A fragment: loaded + split exactly once (owning warp only)
            uint32_t ah[4], al[4];
            tf32split(raw[m][c0],     ah[0], al[0]);
            tf32split(raw[m + 8][c0], ah[1], al[1]);
            tf32split(raw[m][c1],     ah[2], al[2]);
            tf32split(raw[m + 8][c1], ah[3], al[3]);
            #pragma unroll
            for (int n8 = 0; n8 < 8; ++n8) {
                const float4 bv = bF[(k8 * 8 + n8) * 32 + lane];
                uint32_t bh[2] = {__float_as_uint(bv.x), __float_as_uint(bv.y)};
                uint32_t bl[2] = {__float_as_uint(bv.z), __float_as_uint(bv.w)};
                mma8(acc[n8], ah, bh);   // hi*hi
                mma8(acc[n8], ah, bl);   // hi*lo
                mma8(acc[n8], al, bh);   // lo*hi
            }
        }
        __syncthreads();
    }

    // epilogue -> g_part[part]
    float* outp = &g_part[(size_t)part * NN * F1];
    const int r0 = m0 + wid * 16 + g;
    const int r1 = r0 + 8;
    #pragma unroll
    for (int n8 = 0; n8 < 8; ++n8) {
        const int col = n8 * 8 + 2 * t;
        if (r0 < NN) {
            float2 v0 = make_float2(acc[n8][0], acc[n8][1]);
            *reinterpret_cast<float2*>(&outp[(size_t)r0 * F1 + col]) = v0;
        }
        if (r1 < NN) {
            float2 v1 = make_float2(acc[n8][2], acc[n8][3]);
            *reinterpret_cast<float2*>(&outp[(size_t)r1 * F1 + col]) = v1;
        }
    }
}

// reduce split-K partials -> g_bufA, fused self-loop init -> g_bufB
__global__ void reduce_agg_kernel() {
    int idx4 = blockIdx.x * blockDim.x + threadIdx.x;
    if (idx4 < NN * F1 / 4) {
        float4 s = make_float4(0.f, 0.f, 0.f, 0.f);
        #pragma unroll
        for (int p = 0; p < SPLIT; ++p) {
            const float4 v = *reinterpret_cast<const float4*>(
                &g_part[(size_t)p * NN * F1 + (size_t)idx4 * 4]);
            s.x += v.x; s.y += v.y; s.z += v.z; s.w += v.w;
        }
        *reinterpret_cast<float4*>(&g_bufA[(size_t)idx4 * 4]) = s;
        const int row = idx4 / (F1 / 4);
        const float d  = g_dinv[row];
        const float d2 = d * d;
        float4 tt = make_float4(s.x * d2, s.y * d2, s.z * d2, s.w * d2);
        *reinterpret_cast<float4*>(&g_bufB[(size_t)idx4 * 4]) = tt;
    }
}

// ---------------- small GEMMs: g_bufB [NN,64] x W [64,C] -> g_bufA --------
template <int CIN, int C>
__global__ void gemm_small_agg_kernel(const float* __restrict__ W) {
    __shared__ float w_s[CIN * C];
    for (int i = threadIdx.x; i < CIN * C; i += blockDim.x) w_s[i] = W[i];
    __syncthreads();
    const int total  = NN * C;
    const int stride = gridDim.x * blockDim.x;
    for (int idx = blockIdx.x * blockDim.x + threadIdx.x; idx < total; idx += stride) {
        const int row = idx / C;
        const int col = idx % C;
        const float* rp = &g_bufB[(size_t)row * CIN];
        float acc = 0.0f;
        #pragma unroll
        for (int k = 0; k < CIN; ++k) acc += rp[k] * w_s[k * C + col];
        g_bufA[idx] = acc;
    }
}

// self-loop init for layers 2/3
template <int C>
__global__ void agg_init_kernel() {
    int idx4 = blockIdx.x * blockDim.x + threadIdx.x;
    if (idx4 < NN * C / 4) {
        const int row = idx4 / (C / 4);
        const float d  = g_dinv[row];
        const float d2 = d * d;
        const float4 v = *reinterpret_cast<const float4*>(&g_bufA[(size_t)idx4 * 4]);
        float4 tt = make_float4(v.x * d2, v.y * d2, v.z * d2, v.w * d2);
        *reinterpret_cast<float4*>(&g_bufB[(size_t)idx4 * 4]) = tt;
    }
}

// edges: one thread per (edge, 4-col group): float4 gather + red.v4
template <int C>
__global__ void agg_edges_kernel(const int* __restrict__ ei, int E) {
    constexpr int LPE = C / 4;
    const long long t = (long long)blockIdx.x * blockDim.x + threadIdx.x;
    if (t >= (long long)E * LPE) return;
    const int e = (int)(t / LPE);
    const int g = (int)(t % LPE);
    const int src = clampN(ei[e]);
    const int dst = clampN(ei[E + e]);
    const float norm = g_dinv[src] * g_dinv[dst];
    const float4 v = *reinterpret_cast<const float4*>(&g_bufA[(size_t)src * C + g * 4]);
    float* o = &g_bufB[(size_t)dst * C + g * 4];
    asm volatile("red.global.add.v4.f32 [%0], {%1, %2, %3, %4};"
                 :: "l"(o), "f"(v.x * norm), "f"(v.y * norm),
                    "f"(v.z * norm), "f"(v.w * norm)
                 : "memory");
}

// ---------------- epilogues ----------------
template <int C>
__global__ void bias_relu_kernel(const float* __restrict__ b) {
    int idx4 = blockIdx.x * blockDim.x + threadIdx.x;
    if (idx4 < NN * C / 4) {
        const float4 bb = *reinterpret_cast<const float4*>(&b[(idx4 % (C / 4)) * 4]);
        float4 v = *reinterpret_cast<float4*>(&g_bufB[(size_t)idx4 * 4]);
        v.x = fmaxf(v.x + bb.x, 0.f);
        v.y = fmaxf(v.y + bb.y, 0.f);
        v.z = fmaxf(v.z + bb.z, 0.f);
        v.w = fmaxf(v.w + bb.w, 0.f);
        *reinterpret_cast<float4*>(&g_bufB[(size_t)idx4 * 4]) = v;
    }
}

__global__ void softmax_kernel(const float* __restrict__ b, float* __restrict__ out) {
    int r = blockIdx.x * blockDim.x + threadIdx.x;
    if (r >= NN) return;
    float v[COUT];
    float m = -1e30f;
    #pragma unroll
    for (int j = 0; j < COUT; ++j) {
        v[j] = g_bufB[(size_t)r * COUT + j] + b[j];
        m = fmaxf(m, v[j]);
    }
    float s = 0.0f;
    #pragma unroll
    for (int j = 0; j < COUT; ++j) {
        v[j] = expf(v[j] - m);
        s += v[j];
    }
    const float inv = 1.0f / s;
    #pragma unroll
    for (int j = 0; j < COUT; ++j) out[(size_t)r * COUT + j] = v[j] * inv;
}

// ---------------- launch ----------------
extern "C" void kernel_launch(void* const* d_in, const int* in_sizes, int n_in,
                              void* d_out, int out_size) {
    const float* x  = (const float*)d_in[0];
    const int*   ei = (const int*)d_in[1];   // int32 (JAX x64 disabled)
    const float* W1 = (const float*)d_in[2];
    const float* b1 = (const float*)d_in[3];
    const float* W2 = (const float*)d_in[4];
    const float* b2 = (const float*)d_in[5];
    const float* W3 = (const float*)d_in[6];
    const float* b3 = (const float*)d_in[7];
    float* out = (float*)d_out;

    const int E = in_sizes[1] / 2;

    const int T = 256;
    const int gN    = (NN + T - 1) / T;
    const int gE    = (E + T - 1) / T;
    const int g64v  = (NN * F1 / 4 + T - 1) / T;
    const int g16v  = (NN * COUT / 4 + T - 1) / T;
    const int gE64  = (int)(((long long)E * (F1 / 4) + T - 1) / T);
    const int gE16  = (int)(((long long)E * (COUT / 4) + T - 1) / T);
    const dim3 gG((NN + BM - 1) / BM, SPLIT);   // 79 x 4

    // degrees + normalization + W1 prep
    deg_init_kernel<<<gN, T>>>();
    deg_count_kernel<<<gE, T>>>(ei, E);
    dinv_kernel<<<gN, T>>>();
    wfrag_kernel<<<(NCH * 512 + T - 1) / T, T>>>(W1);

    // ---- layer 1 ----
    gemm1_mma_kernel<<<gG, 256>>>(x);
    reduce_agg_kernel<<<g64v, T>>>();              // bufA = sum parts, bufB = self-loop
    agg_edges_kernel<F1><<<gE64, T>>>(ei, E);
    bias_relu_kernel<F1><<<g64v, T>>>(b1);

    // ---- layer 2 ----
    gemm_small_agg_kernel<F1, F1><<<1480, T>>>(W2);
    agg_init_kernel<F1><<<g64v, T>>>();
    agg_edges_kernel<F1><<<gE64, T>>>(ei, E);
    bias_relu_kernel<F1><<<g64v, T>>>(b2);

    // ---- layer 3 ----
    gemm_small_agg_kernel<F1, COUT><<<1480, T>>>(W3);
    agg_init_kernel<COUT><<<g16v, T>>>();
    agg_edges_kernel<COUT><<<gE16, T>>>(ei, E);
    softmax_kernel<<<gN, T>>>(b3, out);
}

// round 10
// speedup vs baseline: 1.3392x; 1.3392x over previous
#include <cuda_runtime.h>
#include <cstdint>

// ---------------- problem constants (fixed-shape problem) ----------------
constexpr int NN   = 10000;  // nodes
constexpr int F1   = 64;     // hidden feat
constexpr int COUT = 16;     // classes

// GEMM1 (mma.sync tf32) tiling  [round-7 structure, verified 440us]
constexpr int BM    = 128;
constexpr int BN    = 64;
constexpr int BK    = 16;
constexpr int SPLIT = 4;
constexpr int NCH   = NN / BK;   // 625 exact -> no K tail
constexpr int LDK   = 20;        // padded k-stride (floats)

// ---------------- device scratch (no allocation; device-code refs only) --
__device__ __align__(16) float g_deg[NN];
__device__ __align__(16) float g_dinv[NN];
__device__ __align__(16) float g_bufA[(size_t)NN * F1];
__device__ __align__(16) float g_bufB[(size_t)NN * F1];
__device__ __align__(16) float g_part[(size_t)SPLIT * NN * F1];
__device__ __align__(16) float g_wt[(size_t)128 * NN];  // rows 0..63 tf32-hi(W1^T), 64..127 tf32-lo

__device__ __forceinline__ int clampN(int v) {
    v = v < 0 ? 0 : v;
    return v < NN ? v : NN - 1;
}

// ---------------- PTX helpers ----------------
__device__ __forceinline__ uint32_t tf32_rna(float f) {
    uint32_t u;
    asm("cvt.rna.tf32.f32 %0, %1;" : "=r"(u) : "f"(f));
    return u;
}
__device__ __forceinline__ void tf32split(float a, uint32_t& hi, uint32_t& lo) {
    hi = tf32_rna(a);
    lo = tf32_rna(a - __uint_as_float(hi));
}
__device__ __forceinline__ void mma8(float* d, const uint32_t* a, const uint32_t* b) {
    asm volatile(
        "mma.sync.aligned.m16n8k8.row.col.f32.tf32.tf32.f32 "
        "{%0,%1,%2,%3},{%4,%5,%6,%7},{%8,%9},{%0,%1,%2,%3};"
        : "+f"(d[0]), "+f"(d[1]), "+f"(d[2]), "+f"(d[3])
        : "r"(a[0]), "r"(a[1]), "r"(a[2]), "r"(a[3]), "r"(b[0]), "r"(b[1]));
}
__device__ __forceinline__ void cp16(uint32_t dst, const void* src) {
    asm volatile("cp.async.cg.shared.global [%0], [%1], 16;" :: "r"(dst), "l"(src));
}

// ---------------- degree / norm ----------------
__global__ void deg_init_kernel() {
    int i = blockIdx.x * blockDim.x + threadIdx.x;
    if (i < NN) g_deg[i] = 1.0f;
}
__global__ void deg_count_kernel(const int* __restrict__ ei, int E) {
    int e = blockIdx.x * blockDim.x + threadIdx.x;
    if (e < E) atomicAdd(&g_deg[clampN(ei[E + e])], 1.0f);
}
__global__ void dinv_kernel() {
    int i = blockIdx.x * blockDim.x + threadIdx.x;
    if (i < NN) g_dinv[i] = rsqrtf(g_deg[i]);
}

// ---------------- W1 transpose + tf32 hi/lo split ----------------
__global__ void transpose_w_kernel(const float* __restrict__ W) {
    __shared__ float t[64][65];
    const int tid = threadIdx.x;
    const int k0  = blockIdx.x * 64;
    for (int i = tid; i < 64 * 64; i += 256) {
        int kk = i >> 6, n = i & 63;
        t[n][kk] = (k0 + kk < NN) ? W[(size_t)(k0 + kk) * 64 + n] : 0.0f;
    }
    __syncthreads();
    for (int i = tid; i < 64 * 64; i += 256) {
        int n = i >> 6, kk = i & 63;
        if (k0 + kk < NN) {
            float w = t[n][kk];
            uint32_t hi, lo;
            tf32split(w, hi, lo);
            g_wt[(size_t)n * NN + k0 + kk]        = __uint_as_float(hi);
            g_wt[(size_t)(64 + n) * NN + k0 + kk] = __uint_as_float(lo);
        }
    }
}

// ---------------- GEMM1: mma.sync tf32 hi/lo, split-K (r7 + term-major) ---
__global__ void __launch_bounds__(256, 2) gemm1_mma_kernel(const float* __restrict__ A) {
    __shared__ __align__(16) float As[2][BM][LDK];    // [stage][m][k]
    __shared__ __align__(16) float Bs[2][128][LDK];   // [stage][hi:0-63|lo:64-127][k]

    const int tid  = threadIdx.x;
    const int lane = tid & 31;
    const int wid  = tid >> 5;
    const int g    = lane >> 2;        // group id (0..7)
    const int t    = lane & 3;         // thread-in-group
    const int wm   = wid >> 2;         // warp m (0..1), tile 64
    const int wn   = wid & 3;          // warp n (0..3), tile 16
    const int m0   = blockIdx.x * BM;
    const int part = blockIdx.y;

    const int q = NCH / SPLIT, r = NCH % SPLIT;
    const int cBeg = part * q + (part < r ? part : r);
    const int nCh  = q + (part < r ? 1 : 0);

    // cp.async mapping: 512 A tasks + 512 B tasks; 2 each per thread
    const int lrow = tid >> 2;           // 0..63
    const int lj   = (tid & 3) * 4;      // k word offset 0,4,8,12
    const int aRow0 = clampN(m0 + lrow);
    const int aRow1 = clampN(m0 + 64 + lrow);
    const float* Ap0 = A + (size_t)aRow0 * NN + lj;
    const float* Ap1 = A + (size_t)aRow1 * NN + lj;
    const float* Bp0 = &g_wt[(size_t)lrow * NN + lj];
    const float* Bp1 = &g_wt[(size_t)(64 + lrow) * NN + lj];

    const uint32_t asb = (uint32_t)__cvta_generic_to_shared(&As[0][0][0]);
    const uint32_t bsb = (uint32_t)__cvta_generic_to_shared(&Bs[0][0][0]);
    const uint32_t aOff0 = (uint32_t)((lrow * LDK + lj) * 4);
    const uint32_t aOff1 = (uint32_t)(((64 + lrow) * LDK + lj) * 4);
    const uint32_t stageA = (uint32_t)(BM * LDK * 4);
    const uint32_t stageB = (uint32_t)(128 * LDK * 4);

    float acc[4][2][4] = {};   // [msub][nsub][reg]

    // prologue: chunk 0 -> stage 0
    {
        const size_t k0 = (size_t)cBeg * BK;
        cp16(asb + aOff0, Ap0 + k0);
        cp16(asb + aOff1, Ap1 + k0);
        cp16(bsb + aOff0, Bp0 + k0);
        cp16(bsb + aOff1, Bp1 + k0);
        asm volatile("cp.async.commit_group;");
    }

    for (int i = 0; i < nCh; ++i) {
        const int s = i & 1;
        if (i + 1 < nCh) {
            const int ns = s ^ 1;
            const size_t k0 = (size_t)(cBeg + i + 1) * BK;
            cp16(asb + ns * stageA + aOff0, Ap0 + k0);
            cp16(asb + ns * stageA + aOff1, Ap1 + k0);
            cp16(bsb + ns * stageB + aOff0, Bp0 + k0);
            cp16(bsb + ns * stageB + aOff1, Bp1 + k0);
            asm volatile("cp.async.commit_group;");
            asm volatile("cp.async.wait_group 1;");
        } else {
            asm volatile("cp.async.wait_group 0;");
        }
        __syncthreads();

        #pragma unroll
        for (int k8 = 0; k8 < 2; ++k8) {
            const int c0 = k8 * 8 + t;
            const int c1 = c0 + 4;

            uint32_t ah[4][4], al[4][4];
            #pragma unroll
            for (int ms = 0; ms < 4; ++ms) {
                const int r0 = wm * 64 + ms * 16 + g;
                const float a0 = As[s][r0][c0];
                const float a1 = As[s][r0 + 8][c0];
                const float a2 = As[s][r0][c1];
                const float a3 = As[s][r0 + 8][c1];
                tf32split(a0, ah[ms][0], al[ms][0]);
                tf32split(a1, ah[ms][1], al[ms][1]);
                tf32split(a2, ah[ms][2], al[ms][2]);
                tf32split(a3, ah[ms][3], al[ms][3]);
            }
            uint32_t bh[2][2], bl[2][2];
            #pragma unroll
            for (int ns = 0; ns < 2; ++ns) {
                const int n = wn * 16 + ns * 8 + g;
                bh[ns][0] = __float_as_uint(Bs[s][n][c0]);
                bh[ns][1] = __float_as_uint(Bs[s][n][c1]);
                bl[ns][0] = __float_as_uint(Bs[s][64 + n][c0]);
                bl[ns][1] = __float_as_uint(Bs[s][64 + n][c1]);
            }
            // term-major passes: consecutive MMAs hit 8 independent accumulators;
            // per-accumulator term order (hh, hl, lh) unchanged -> identical numerics
            #pragma unroll
            for (int ms = 0; ms < 4; ++ms)
                #pragma unroll
                for (int ns = 0; ns < 2; ++ns)
                    mma8(acc[ms][ns], ah[ms], bh[ns]);   // hi*hi
            #pragma unroll
            for (int ms = 0; ms < 4; ++ms)
                #pragma unroll
                for (int ns = 0; ns < 2; ++ns)
                    mma8(acc[ms][ns], ah[ms], bl[ns]);   // hi*lo
            #pragma unroll
            for (int ms = 0; ms < 4; ++ms)
                #pragma unroll
                for (int ns = 0; ns < 2; ++ns)
                    mma8(acc[ms][ns], al[ms], bh[ns]);   // lo*hi
        }
        __syncthreads();
    }

    // epilogue -> g_part[part]
    float* outp = &g_part[(size_t)part * NN * F1];
    #pragma unroll
    for (int ms = 0; ms < 4; ++ms) {
        #pragma unroll
        for (int ns = 0; ns < 2; ++ns) {
            const int col = wn * 16 + ns * 8 + 2 * t;
            const int r0  = m0 + wm * 64 + ms * 16 + g;
            if (r0 < NN) {
                float2 v0 = make_float2(acc[ms][ns][0], acc[ms][ns][1]);
                *reinterpret_cast<float2*>(&outp[(size_t)r0 * F1 + col]) = v0;
            }
            const int r1 = r0 + 8;
            if (r1 < NN) {
                float2 v1 = make_float2(acc[ms][ns][2], acc[ms][ns][3]);
                *reinterpret_cast<float2*>(&outp[(size_t)r1 * F1 + col]) = v1;
            }
        }
    }
}

// reduce split-K partials -> g_bufA, fused self-loop init -> g_bufB
__global__ void reduce_agg_kernel() {
    int idx4 = blockIdx.x * blockDim.x + threadIdx.x;
    if (idx4 < NN * F1 / 4) {
        float4 s = make_float4(0.f, 0.f, 0.f, 0.f);
        #pragma unroll
        for (int p = 0; p < SPLIT; ++p) {
            const float4 v = *reinterpret_cast<const float4*>(
                &g_part[(size_t)p * NN * F1 + (size_t)idx4 * 4]);
            s.x += v.x; s.y += v.y; s.z += v.z; s.w += v.w;
        }
        *reinterpret_cast<float4*>(&g_bufA[(size_t)idx4 * 4]) = s;
        const int row = idx4 / (F1 / 4);
        const float d  = g_dinv[row];
        const float d2 = d * d;
        float4 tt = make_float4(s.x * d2, s.y * d2, s.z * d2, s.w * d2);
        *reinterpret_cast<float4*>(&g_bufB[(size_t)idx4 * 4]) = tt;
    }
}

// ---------------- small GEMMs: g_bufB [NN,64] x W [64,C] -> g_bufA --------
template <int CIN, int C>
__global__ void gemm_small_agg_kernel(const float* __restrict__ W) {
    __shared__ float w_s[CIN * C];
    for (int i = threadIdx.x; i < CIN * C; i += blockDim.x) w_s[i] = W[i];
    __syncthreads();
    const int total  = NN * C;
    const int stride = gridDim.x * blockDim.x;
    for (int idx = blockIdx.x * blockDim.x + threadIdx.x; idx < total; idx += stride) {
        const int row = idx / C;
        const int col = idx % C;
        const float* rp = &g_bufB[(size_t)row * CIN];
        float acc = 0.0f;
        #pragma unroll
        for (int k = 0; k < CIN; ++k) acc += rp[k] * w_s[k * C + col];
        g_bufA[idx] = acc;
    }
}

// self-loop init for layers 2/3
template <int C>
__global__ void agg_init_kernel() {
    int idx4 = blockIdx.x * blockDim.x + threadIdx.x;
    if (idx4 < NN * C / 4) {
        const int row = idx4 / (C / 4);
        const float d  = g_dinv[row];
        const float d2 = d * d;
        const float4 v = *reinterpret_cast<const float4*>(&g_bufA[(size_t)idx4 * 4]);
        float4 tt = make_float4(v.x * d2, v.y * d2, v.z * d2, v.w * d2);
        *reinterpret_cast<float4*>(&g_bufB[(size_t)idx4 * 4]) = tt;
    }
}

// edges: one thread per (edge, 4-col group): float4 gather + red.v4
template <int C>
__global__ void agg_edges_kernel(const int* __restrict__ ei, int E) {
    constexpr int LPE = C / 4;
    const long long t = (long long)blockIdx.x * blockDim.x + threadIdx.x;
    if (t >= (long long)E * LPE) return;
    const int e = (int)(t / LPE);
    const int g = (int)(t % LPE);
    const int src = clampN(ei[e]);
    const int dst = clampN(ei[E + e]);
    const float norm = g_dinv[src] * g_dinv[dst];
    const float4 v = *reinterpret_cast<const float4*>(&g_bufA[(size_t)src * C + g * 4]);
    float* o = &g_bufB[(size_t)dst * C + g * 4];
    asm volatile("red.global.add.v4.f32 [%0], {%1, %2, %3, %4};"
                 :: "l"(o), "f"(v.x * norm), "f"(v.y * norm),
                    "f"(v.z * norm), "f"(v.w * norm)
                 : "memory");
}

// ---------------- epilogues ----------------
template <int C>
__global__ void bias_relu_kernel(const float* __restrict__ b) {
    int idx4 = blockIdx.x * blockDim.x + threadIdx.x;
    if (idx4 < NN * C / 4) {
        const float4 bb = *reinterpret_cast<const float4*>(&b[(idx4 % (C / 4)) * 4]);
        float4 v = *reinterpret_cast<float4*>(&g_bufB[(size_t)idx4 * 4]);
        v.x = fmaxf(v.x + bb.x, 0.f);
        v.y = fmaxf(v.y + bb.y, 0.f);
        v.z = fmaxf(v.z + bb.z, 0.f);
        v.w = fmaxf(v.w + bb.w, 0.f);
        *reinterpret_cast<float4*>(&g_bufB[(size_t)idx4 * 4]) = v;
    }
}

__global__ void softmax_kernel(const float* __restrict__ b, float* __restrict__ out) {
    int r = blockIdx.x * blockDim.x + threadIdx.x;
    if (r >= NN) return;
    float v[COUT];
    float m = -1e30f;
    #pragma unroll
    for (int j = 0; j < COUT; ++j) {
        v[j] = g_bufB[(size_t)r * COUT + j] + b[j];
        m = fmaxf(m, v[j]);
    }
    float s = 0.0f;
    #pragma unroll
    for (int j = 0; j < COUT; ++j) {
        v[j] = expf(v[j] - m);
        s += v[j];
    }
    const float inv = 1.0f / s;
    #pragma unroll
    for (int j = 0; j < COUT; ++j) out[(size_t)r * COUT + j] = v[j] * inv;
}

// ---------------- launch ----------------
extern "C" void kernel_launch(void* const* d_in, const int* in_sizes, int n_in,
                              void* d_out, int out_size) {
    const float* x  = (const float*)d_in[0];
    const int*   ei = (const int*)d_in[1];   // int32 (JAX x64 disabled)
    const float* W1 = (const float*)d_in[2];
    const float* b1 = (const float*)d_in[3];
    const float* W2 = (const float*)d_in[4];
    const float* b2 = (const float*)d_in[5];
    const float* W3 = (const float*)d_in[6];
    const float* b3 = (const float*)d_in[7];
    float* out = (float*)d_out;

    const int E = in_sizes[1] / 2;

    const int T = 256;
    const int gN    = (NN + T - 1) / T;
    const int gE    = (E + T - 1) / T;
    const int g64v  = (NN * F1 / 4 + T - 1) / T;
    const int g16v  = (NN * COUT / 4 + T - 1) / T;
    const int gE64  = (int)(((long long)E * (F1 / 4) + T - 1) / T);
    const int gE16  = (int)(((long long)E * (COUT / 4) + T - 1) / T);
    const dim3 gG((NN + BM - 1) / BM, SPLIT);   // 79 x 4

    // degrees + normalization + W1 prep
    deg_init_kernel<<<gN, T>>>();
    deg_count_kernel<<<gE, T>>>(ei, E);
    dinv_kernel<<<gN, T>>>();
    transpose_w_kernel<<<(NN + 63) / 64, 256>>>(W1);

    // ---- layer 1 ----
    gemm1_mma_kernel<<<gG, 256>>>(x);
    reduce_agg_kernel<<<g64v, T>>>();              // bufA = sum parts, bufB = self-loop
    agg_edges_kernel<F1><<<gE64, T>>>(ei, E);
    bias_relu_kernel<F1><<<g64v, T>>>(b1);

    // ---- layer 2 ----
    gemm_small_agg_kernel<F1, F1><<<1480, T>>>(W2);
    agg_init_kernel<F1><<<g64v, T>>>();
    agg_edges_kernel<F1><<<gE64, T>>>(ei, E);
    bias_relu_kernel<F1><<<g64v, T>>>(b2);

    // ---- layer 3 ----
    gemm_small_agg_kernel<F1, COUT><<<1480, T>>>(W3);
    agg_init_kernel<COUT><<<g16v, T>>>();
    agg_edges_kernel<COUT><<<gE16, T>>>(ei, E);
    softmax_kernel<<<gN, T>>>(b3, out);
}

// round 11
// speedup vs baseline: 1.8014x; 1.3451x over previous
#include <cuda_runtime.h>
#include <cstdint>

// ---------------- problem constants (fixed-shape problem) ----------------
constexpr int NN   = 10000;  // nodes
constexpr int F1   = 64;     // hidden feat
constexpr int COUT = 16;     // classes

// GEMM1 (mma.sync bf16 m16n8k16 hi/lo) tiling [round-7 skeleton]
constexpr int BM    = 128;
constexpr int BK    = 16;
constexpr int SPLIT = 4;
constexpr int NCH   = NN / BK;   // 625 exact -> no K tail
constexpr int LDK   = 20;        // padded k-stride (floats)

// ---------------- device scratch (no allocation; device-code refs only) --
__device__ __align__(16) float g_deg[NN];
__device__ __align__(16) float g_dinv[NN];
__device__ __align__(16) float g_bufA[(size_t)NN * F1];
__device__ __align__(16) float g_bufB[(size_t)NN * F1];
__device__ __align__(16) float g_part[(size_t)SPLIT * NN * F1];
// B fragments: per chunk, per n8(8), per lane(32): uint4 {b0h, b1h, b0l, b1l}
__device__ __align__(16) uint4 g_wbf[(size_t)NCH * 256];

__device__ __forceinline__ int clampN(int v) {
    v = v < 0 ? 0 : v;
    return v < NN ? v : NN - 1;
}

// ---------------- PTX helpers ----------------
// pack {bf16(hiw) : upper16, bf16(low) : lower16}
__device__ __forceinline__ uint32_t packbf(float hiw, float low) {
    uint32_t r;
    asm("cvt.rn.bf16x2.f32 %0, %1, %2;" : "=r"(r) : "f"(hiw), "f"(low));
    return r;
}
// split two fp32 (e0 -> lower half, e1 -> upper half) into bf16 hi + bf16 residual
__device__ __forceinline__ void bfsplit2(float e0, float e1, uint32_t& hi, uint32_t& lo) {
    hi = packbf(e1, e0);
    const float h0 = __uint_as_float(hi << 16);
    const float h1 = __uint_as_float(hi & 0xFFFF0000u);
    lo = packbf(e1 - h1, e0 - h0);
}
__device__ __forceinline__ void mma16(float* d, const uint32_t* a, const uint32_t* b) {
    asm volatile(
        "mma.sync.aligned.m16n8k16.row.col.f32.bf16.bf16.f32 "
        "{%0,%1,%2,%3},{%4,%5,%6,%7},{%8,%9},{%0,%1,%2,%3};"
        : "+f"(d[0]), "+f"(d[1]), "+f"(d[2]), "+f"(d[3])
        : "r"(a[0]), "r"(a[1]), "r"(a[2]), "r"(a[3]), "r"(b[0]), "r"(b[1]));
}
__device__ __forceinline__ void cp16(uint32_t dst, const void* src) {
    asm volatile("cp.async.cg.shared.global [%0], [%1], 16;" :: "r"(dst), "l"(src));
}

// ---------------- degree / norm ----------------
__global__ void deg_init_kernel() {
    int i = blockIdx.x * blockDim.x + threadIdx.x;
    if (i < NN) g_deg[i] = 1.0f;
}
__global__ void deg_count_kernel(const int* __restrict__ ei, int E) {
    int e = blockIdx.x * blockDim.x + threadIdx.x;
    if (e < E) atomicAdd(&g_deg[clampN(ei[E + e])], 1.0f);
}
__global__ void dinv_kernel() {
    int i = blockIdx.x * blockDim.x + threadIdx.x;
    if (i < NN) g_dinv[i] = rsqrtf(g_deg[i]);
}

// ---------------- W1 -> fragment-order packed bf16 hi/lo ----------------
// idx = c*256 + n8*32 + lane; g=lane>>2, t=lane&3, n=n8*8+g, k0=c*16
// b0 = {W[k0+2t][n], W[k0+2t+1][n]}, b1 = {W[k0+2t+8][n], W[k0+2t+9][n]}
__global__ void wfrag_kernel(const float* __restrict__ W) {
    int idx = blockIdx.x * blockDim.x + threadIdx.x;
    if (idx >= NCH * 256) return;
    const int lane = idx & 31;
    const int n8   = (idx >> 5) & 7;
    const int c    = idx >> 8;
    const int g = lane >> 2, t = lane & 3;
    const int n  = n8 * 8 + g;
    const int k0 = c * 16 + 2 * t;
    const float w00 = W[(size_t)k0 * 64 + n];
    const float w01 = W[(size_t)(k0 + 1) * 64 + n];
    const float w10 = W[(size_t)(k0 + 8) * 64 + n];
    const float w11 = W[(size_t)(k0 + 9) * 64 + n];
    uint32_t b0h, b0l, b1h, b1l;
    bfsplit2(w00, w01, b0h, b0l);
    bfsplit2(w10, w11, b1h, b1l);
    uint4 v;
    v.x = b0h; v.y = b1h; v.z = b0l; v.w = b1l;
    g_wbf[idx] = v;
}

// ---------------- GEMM1: mma.sync bf16 hi/lo, split-K ----------------
__global__ void __launch_bounds__(256, 2) gemm1_mma_kernel(const float* __restrict__ A) {
    __shared__ __align__(16) float As[2][BM][LDK];   // raw fp32 A tiles
    __shared__ __align__(16) uint4 Bf[2][256];       // B fragments (hi/lo packed)

    const int tid  = threadIdx.x;
    const int lane = tid & 31;
    const int wid  = tid >> 5;
    const int g    = lane >> 2;        // group id (0..7)
    const int t    = lane & 3;         // thread-in-group
    const int wm   = wid >> 2;         // warp m (0..1), tile 64
    const int wn   = wid & 3;          // warp n (0..3), tile 16
    const int m0   = blockIdx.x * BM;
    const int part = blockIdx.y;

    const int q = NCH / SPLIT, r = NCH % SPLIT;
    const int cBeg = part * q + (part < r ? part : r);
    const int nCh  = q + (part < r ? 1 : 0);

    // loaders: A 512 cp16 tasks (2/thread), B 256 cp16 tasks (1/thread)
    const int am0 = tid >> 2,         aj0 = (tid & 3) * 4;
    const int am1 = (tid + 256) >> 2, aj1 = ((tid + 256) & 3) * 4;
    const float* Ap0 = A + (size_t)clampN(m0 + am0) * NN + aj0;
    const float* Ap1 = A + (size_t)clampN(m0 + am1) * NN + aj1;

    const uint32_t aDst0 = (uint32_t)__cvta_generic_to_shared(&As[0][am0][aj0]);
    const uint32_t aDst1 = (uint32_t)__cvta_generic_to_shared(&As[0][am1][aj1]);
    const uint32_t bDst  = (uint32_t)__cvta_generic_to_shared(&Bf[0][0]);
    const uint32_t stageA = (uint32_t)(BM * LDK * 4);
    const uint32_t stageB = 4096u;

    float acc[4][2][4] = {};   // [msub][nsub][reg]

    // prologue: chunk cBeg -> stage 0
    {
        const size_t kf = (size_t)cBeg * BK;
        cp16(aDst0, Ap0 + kf);
        cp16(aDst1, Ap1 + kf);
        cp16(bDst + (uint32_t)tid * 16, &g_wbf[(size_t)cBeg * 256 + tid]);
        asm volatile("cp.async.commit_group;");
    }

    for (int i = 0; i < nCh; ++i) {
        const int s = i & 1;
        if (i + 1 < nCh) {
            const uint32_t ns = (uint32_t)(s ^ 1);
            const size_t kf = (size_t)(cBeg + i + 1) * BK;
            cp16(aDst0 + ns * stageA, Ap0 + kf);
            cp16(aDst1 + ns * stageA, Ap1 + kf);
            cp16(bDst + ns * stageB + (uint32_t)tid * 16,
                 &g_wbf[(size_t)(cBeg + i + 1) * 256 + tid]);
            asm volatile("cp.async.commit_group;");
            asm volatile("cp.async.wait_group 1;");
        } else {
            asm volatile("cp.async.wait_group 0;");
        }
        __syncthreads();

        // B fragments for this warp's two n8 strips
        uint32_t bh[2][2], bl[2][2];
        #pragma unroll
        for (int ns = 0; ns < 2; ++ns) {
            const uint4 bv = Bf[s][(wn * 2 + ns) * 32 + lane];
            bh[ns][0] = bv.x; bh[ns][1] = bv.y;
            bl[ns][0] = bv.z; bl[ns][1] = bv.w;
        }

        #pragma unroll
        for (int ms = 0; ms < 4; ++ms) {
            const int r0 = wm * 64 + ms * 16 + g;
            const float2 p0 = *reinterpret_cast<const float2*>(&As[s][r0][2 * t]);
            const float2 p1 = *reinterpret_cast<const float2*>(&As[s][r0 + 8][2 * t]);
            const float2 p2 = *reinterpret_cast<const float2*>(&As[s][r0][2 * t + 8]);
            const float2 p3 = *reinterpret_cast<const float2*>(&As[s][r0 + 8][2 * t + 8]);
            uint32_t ah[4], al[4];
            bfsplit2(p0.x, p0.y, ah[0], al[0]);
            bfsplit2(p1.x, p1.y, ah[1], al[1]);
            bfsplit2(p2.x, p2.y, ah[2], al[2]);
            bfsplit2(p3.x, p3.y, ah[3], al[3]);
            #pragma unroll
            for (int ns = 0; ns < 2; ++ns) {
                mma16(acc[ms][ns], ah, bh[ns]);   // hi*hi
                mma16(acc[ms][ns], ah, bl[ns]);   // hi*lo
                mma16(acc[ms][ns], al, bh[ns]);   // lo*hi
            }
        }
        __syncthreads();
    }

    // epilogue -> g_part[part]  (same c-fragment layout as k8 variant)
    float* outp = &g_part[(size_t)part * NN * F1];
    #pragma unroll
    for (int ms = 0; ms < 4; ++ms) {
        #pragma unroll
        for (int ns = 0; ns < 2; ++ns) {
            const int col = wn * 16 + ns * 8 + 2 * t;
            const int r0  = m0 + wm * 64 + ms * 16 + g;
            if (r0 < NN) {
                float2 v0 = make_float2(acc[ms][ns][0], acc[ms][ns][1]);
                *reinterpret_cast<float2*>(&outp[(size_t)r0 * F1 + col]) = v0;
            }
            const int r1 = r0 + 8;
            if (r1 < NN) {
                float2 v1 = make_float2(acc[ms][ns][2], acc[ms][ns][3]);
                *reinterpret_cast<float2*>(&outp[(size_t)r1 * F1 + col]) = v1;
            }
        }
    }
}

// reduce split-K partials -> g_bufA, fused self-loop init -> g_bufB
__global__ void reduce_agg_kernel() {
    int idx4 = blockIdx.x * blockDim.x + threadIdx.x;
    if (idx4 < NN * F1 / 4) {
        float4 s = make_float4(0.f, 0.f, 0.f, 0.f);
        #pragma unroll
        for (int p = 0; p < SPLIT; ++p) {
            const float4 v = *reinterpret_cast<const float4*>(
                &g_part[(size_t)p * NN * F1 + (size_t)idx4 * 4]);
            s.x += v.x; s.y += v.y; s.z += v.z; s.w += v.w;
        }
        *reinterpret_cast<float4*>(&g_bufA[(size_t)idx4 * 4]) = s;
        const int row = idx4 / (F1 / 4);
        const float d  = g_dinv[row];
        const float d2 = d * d;
        float4 tt = make_float4(s.x * d2, s.y * d2, s.z * d2, s.w * d2);
        *reinterpret_cast<float4*>(&g_bufB[(size_t)idx4 * 4]) = tt;
    }
}

// ---------------- small GEMMs: g_bufB [NN,64] x W [64,C] -> g_bufA --------
template <int CIN, int C>
__global__ void gemm_small_agg_kernel(const float* __restrict__ W) {
    __shared__ float w_s[CIN * C];
    for (int i = threadIdx.x; i < CIN * C; i += blockDim.x) w_s[i] = W[i];
    __syncthreads();
    const int total  = NN * C;
    const int stride = gridDim.x * blockDim.x;
    for (int idx = blockIdx.x * blockDim.x + threadIdx.x; idx < total; idx += stride) {
        const int row = idx / C;
        const int col = idx % C;
        const float* rp = &g_bufB[(size_t)row * CIN];
        float acc = 0.0f;
        #pragma unroll
        for (int k = 0; k < CIN; ++k) acc += rp[k] * w_s[k * C + col];
        g_bufA[idx] = acc;
    }
}

// self-loop init for layers 2/3
template <int C>
__global__ void agg_init_kernel() {
    int idx4 = blockIdx.x * blockDim.x + threadIdx.x;
    if (idx4 < NN * C / 4) {
        const int row = idx4 / (C / 4);
        const float d  = g_dinv[row];
        const float d2 = d * d;
        const float4 v = *reinterpret_cast<const float4*>(&g_bufA[(size_t)idx4 * 4]);
        float4 tt = make_float4(v.x * d2, v.y * d2, v.z * d2, v.w * d2);
        *reinterpret_cast<float4*>(&g_bufB[(size_t)idx4 * 4]) = tt;
    }
}

// edges: one thread per (edge, 4-col group): float4 gather + red.v4
template <int C>
__global__ void agg_edges_kernel(const int* __restrict__ ei, int E) {
    constexpr int LPE = C / 4;
    const long long t = (long long)blockIdx.x * blockDim.x + threadIdx.x;
    if (t >= (long long)E * LPE) return;
    const int e = (int)(t / LPE);
    const int g = (int)(t % LPE);
    const int src = clampN(ei[e]);
    const int dst = clampN(ei[E + e]);
    const float norm = g_dinv[src] * g_dinv[dst];
    const float4 v = *reinterpret_cast<const float4*>(&g_bufA[(size_t)src * C + g * 4]);
    float* o = &g_bufB[(size_t)dst * C + g * 4];
    asm volatile("red.global.add.v4.f32 [%0], {%1, %2, %3, %4};"
                 :: "l"(o), "f"(v.x * norm), "f"(v.y * norm),
                    "f"(v.z * norm), "f"(v.w * norm)
                 : "memory");
}

// ---------------- epilogues ----------------
template <int C>
__global__ void bias_relu_kernel(const float* __restrict__ b) {
    int idx4 = blockIdx.x * blockDim.x + threadIdx.x;
    if (idx4 < NN * C / 4) {
        const float4 bb = *reinterpret_cast<const float4*>(&b[(idx4 % (C / 4)) * 4]);
        float4 v = *reinterpret_cast<float4*>(&g_bufB[(size_t)idx4 * 4]);
        v.x = fmaxf(v.x + bb.x, 0.f);
        v.y = fmaxf(v.y + bb.y, 0.f);
        v.z = fmaxf(v.z + bb.z, 0.f);
        v.w = fmaxf(v.w + bb.w, 0.f);
        *reinterpret_cast<float4*>(&g_bufB[(size_t)idx4 * 4]) = v;
    }
}

__global__ void softmax_kernel(const float* __restrict__ b, float* __restrict__ out) {
    int r = blockIdx.x * blockDim.x + threadIdx.x;
    if (r >= NN) return;
    float v[COUT];
    float m = -1e30f;
    #pragma unroll
    for (int j = 0; j < COUT; ++j) {
        v[j] = g_bufB[(size_t)r * COUT + j] + b[j];
        m = fmaxf(m, v[j]);
    }
    float s = 0.0f;
    #pragma unroll
    for (int j = 0; j < COUT; ++j) {
        v[j] = expf(v[j] - m);
        s += v[j];
    }
    const float inv = 1.0f / s;
    #pragma unroll
    for (int j = 0; j < COUT; ++j) out[(size_t)r * COUT + j] = v[j] * inv;
}

// ---------------- launch ----------------
extern "C" void kernel_launch(void* const* d_in, const int* in_sizes, int n_in,
                              void* d_out, int out_size) {
    const float* x  = (const float*)d_in[0];
    const int*   ei = (const int*)d_in[1];   // int32 (JAX x64 disabled)
    const float* W1 = (const float*)d_in[2];
    const float* b1 = (const float*)d_in[3];
    const float* W2 = (const float*)d_in[4];
    const float* b2 = (const float*)d_in[5];
    const float* W3 = (const float*)d_in[6];
    const float* b3 = (const float*)d_in[7];
    float* out = (float*)d_out;

    const int E = in_sizes[1] / 2;

    const int T = 256;
    const int gN    = (NN + T - 1) / T;
    const int gE    = (E + T - 1) / T;
    const int g64v  = (NN * F1 / 4 + T - 1) / T;
    const int g16v  = (NN * COUT / 4 + T - 1) / T;
    const int gE64  = (int)(((long long)E * (F1 / 4) + T - 1) / T);
    const int gE16  = (int)(((long long)E * (COUT / 4) + T - 1) / T);
    const dim3 gG((NN + BM - 1) / BM, SPLIT);   // 79 x 4

    // degrees + normalization + W1 prep
    deg_init_kernel<<<gN, T>>>();
    deg_count_kernel<<<gE, T>>>(ei, E);
    dinv_kernel<<<gN, T>>>();
    wfrag_kernel<<<(NCH * 256 + T - 1) / T, T>>>(W1);

    // ---- layer 1 ----
    gemm1_mma_kernel<<<gG, 256>>>(x);
    reduce_agg_kernel<<<g64v, T>>>();              // bufA = sum parts, bufB = self-loop
    agg_edges_kernel<F1><<<gE64, T>>>(ei, E);
    bias_relu_kernel<F1><<<g64v, T>>>(b1);

    // ---- layer 2 ----
    gemm_small_agg_kernel<F1, F1><<<1480, T>>>(W2);
    agg_init_kernel<F1><<<g64v, T>>>();
    agg_edges_kernel<F1><<<gE64, T>>>(ei, E);
    bias_relu_kernel<F1><<<g64v, T>>>(b2);

    // ---- layer 3 ----
    gemm_small_agg_kernel<F1, COUT><<<1480, T>>>(W3);
    agg_init_kernel<COUT><<<g16v, T>>>();
    agg_edges_kernel<COUT><<<gE16, T>>>(ei, E);
    softmax_kernel<<<gN, T>>>(b3, out);
}

// round 12
// speedup vs baseline: 2.0802x; 1.1548x over previous
#include <cuda_runtime.h>
#include <cstdint>

// ---------------- problem constants (fixed-shape problem) ----------------
constexpr int NN   = 10000;  // nodes
constexpr int F1   = 64;     // hidden feat
constexpr int COUT = 16;     // classes

// GEMM1 (mma.sync bf16 m16n8k16 hi/lo) tiling
constexpr int BM    = 128;
constexpr int BK    = 16;
constexpr int SPLIT = 8;
constexpr int NCH   = NN / BK;   // 625 exact -> no K tail
constexpr int LDK   = 20;        // padded k-stride (floats)

// ---------------- device scratch (no allocation; device-code refs only) --
__device__ __align__(16) float g_deg[NN];
__device__ __align__(16) float g_dinv[NN];
__device__ __align__(16) float g_bufA[(size_t)NN * F1];
__device__ __align__(16) float g_bufB[(size_t)NN * F1];
__device__ __align__(16) float g_part[(size_t)SPLIT * NN * F1];
// B fragments: per chunk, per n8(8), per lane(32): uint4 {b0h, b1h, b0l, b1l}
__device__ __align__(16) uint4 g_wbf[(size_t)NCH * 256];

__device__ __forceinline__ int clampN(int v) {
    v = v < 0 ? 0 : v;
    return v < NN ? v : NN - 1;
}

// ---------------- PTX helpers ----------------
// pack {bf16(hiw) : upper16, bf16(low) : lower16}
__device__ __forceinline__ uint32_t packbf(float hiw, float low) {
    uint32_t r;
    asm("cvt.rn.bf16x2.f32 %0, %1, %2;" : "=r"(r) : "f"(hiw), "f"(low));
    return r;
}
// split two fp32 (e0 -> lower half, e1 -> upper half) into bf16 hi + bf16 residual
__device__ __forceinline__ void bfsplit2(float e0, float e1, uint32_t& hi, uint32_t& lo) {
    hi = packbf(e1, e0);
    const float h0 = __uint_as_float(hi << 16);
    const float h1 = __uint_as_float(hi & 0xFFFF0000u);
    lo = packbf(e1 - h1, e0 - h0);
}
__device__ __forceinline__ void mma16(float* d, const uint32_t* a, const uint32_t* b) {
    asm volatile(
        "mma.sync.aligned.m16n8k16.row.col.f32.bf16.bf16.f32 "
        "{%0,%1,%2,%3},{%4,%5,%6,%7},{%8,%9},{%0,%1,%2,%3};"
        : "+f"(d[0]), "+f"(d[1]), "+f"(d[2]), "+f"(d[3])
        : "r"(a[0]), "r"(a[1]), "r"(a[2]), "r"(a[3]), "r"(b[0]), "r"(b[1]));
}
__device__ __forceinline__ void cp16(uint32_t dst, const void* src) {
    asm volatile("cp.async.cg.shared.global [%0], [%1], 16;" :: "r"(dst), "l"(src));
}

// ---------------- degree / norm ----------------
__global__ void deg_init_kernel() {
    int i = blockIdx.x * blockDim.x + threadIdx.x;
    if (i < NN) g_deg[i] = 1.0f;
}
__global__ void deg_count_kernel(const int* __restrict__ ei, int E) {
    int e = blockIdx.x * blockDim.x + threadIdx.x;
    if (e < E) atomicAdd(&g_deg[clampN(ei[E + e])], 1.0f);
}
__global__ void dinv_kernel() {
    int i = blockIdx.x * blockDim.x + threadIdx.x;
    if (i < NN) g_dinv[i] = rsqrtf(g_deg[i]);
}

// ---------------- W1 -> fragment-order packed bf16 hi/lo [verified r11] ---
__global__ void wfrag_kernel(const float* __restrict__ W) {
    int idx = blockIdx.x * blockDim.x + threadIdx.x;
    if (idx >= NCH * 256) return;
    const int lane = idx & 31;
    const int n8   = (idx >> 5) & 7;
    const int c    = idx >> 8;
    const int g = lane >> 2, t = lane & 3;
    const int n  = n8 * 8 + g;
    const int k0 = c * 16 + 2 * t;
    const float w00 = W[(size_t)k0 * 64 + n];
    const float w01 = W[(size_t)(k0 + 1) * 64 + n];
    const float w10 = W[(size_t)(k0 + 8) * 64 + n];
    const float w11 = W[(size_t)(k0 + 9) * 64 + n];
    uint32_t b0h, b0l, b1h, b1l;
    bfsplit2(w00, w01, b0h, b0l);
    bfsplit2(w10, w11, b1h, b1l);
    uint4 v;
    v.x = b0h; v.y = b1h; v.z = b0l; v.w = b1l;
    g_wbf[idx] = v;
}

// ---------------- GEMM1: mma.sync bf16 hi/lo, split-K, term-major ---------
__global__ void __launch_bounds__(256, 2) gemm1_mma_kernel(const float* __restrict__ A) {
    __shared__ __align__(16) float As[2][BM][LDK];   // raw fp32 A tiles
    __shared__ __align__(16) uint4 Bf[2][256];       // B fragments (hi/lo packed)

    const int tid  = threadIdx.x;
    const int lane = tid & 31;
    const int wid  = tid >> 5;
    const int g    = lane >> 2;        // group id (0..7)
    const int t    = lane & 3;         // thread-in-group
    const int wm   = wid >> 2;         // warp m (0..1), tile 64
    const int wn   = wid & 3;          // warp n (0..3), tile 16
    const int m0   = blockIdx.x * BM;
    const int part = blockIdx.y;

    const int q = NCH / SPLIT, r = NCH % SPLIT;
    const int cBeg = part * q + (part < r ? part : r);
    const int nCh  = q + (part < r ? 1 : 0);

    // loaders: A 512 cp16 tasks (2/thread), B 256 cp16 tasks (1/thread)
    const int am0 = tid >> 2,         aj0 = (tid & 3) * 4;
    const int am1 = (tid + 256) >> 2, aj1 = ((tid + 256) & 3) * 4;
    const float* Ap0 = A + (size_t)clampN(m0 + am0) * NN + aj0;
    const float* Ap1 = A + (size_t)clampN(m0 + am1) * NN + aj1;

    const uint32_t aDst0 = (uint32_t)__cvta_generic_to_shared(&As[0][am0][aj0]);
    const uint32_t aDst1 = (uint32_t)__cvta_generic_to_shared(&As[0][am1][aj1]);
    const uint32_t bDst  = (uint32_t)__cvta_generic_to_shared(&Bf[0][0]);
    const uint32_t stageA = (uint32_t)(BM * LDK * 4);
    const uint32_t stageB = 4096u;

    float acc[4][2][4] = {};   // [msub][nsub][reg]

    // prologue: chunk cBeg -> stage 0
    {
        const size_t kf = (size_t)cBeg * BK;
        cp16(aDst0, Ap0 + kf);
        cp16(aDst1, Ap1 + kf);
        cp16(bDst + (uint32_t)tid * 16, &g_wbf[(size_t)cBeg * 256 + tid]);
        asm volatile("cp.async.commit_group;");
    }

    for (int i = 0; i < nCh; ++i) {
        const int s = i & 1;
        if (i + 1 < nCh) {
            const uint32_t ns = (uint32_t)(s ^ 1);
            const size_t kf = (size_t)(cBeg + i + 1) * BK;
            cp16(aDst0 + ns * stageA, Ap0 + kf);
            cp16(aDst1 + ns * stageA, Ap1 + kf);
            cp16(bDst + ns * stageB + (uint32_t)tid * 16,
                 &g_wbf[(size_t)(cBeg + i + 1) * 256 + tid]);
            asm volatile("cp.async.commit_group;");
            asm volatile("cp.async.wait_group 1;");
        } else {
            asm volatile("cp.async.wait_group 0;");
        }
        __syncthreads();

        // B fragments for this warp's two n8 strips
        uint32_t bh[2][2], bl[2][2];
        #pragma unroll
        for (int ns = 0; ns < 2; ++ns) {
            const uint4 bv = Bf[s][(wn * 2 + ns) * 32 + lane];
            bh[ns][0] = bv.x; bh[ns][1] = bv.y;
            bl[ns][0] = bv.z; bl[ns][1] = bv.w;
        }

        // all A splits first (once per ms), then term-major MMA passes:
        // consecutive MMAs hit independent accumulators; per-acc term order
        // (hh, hl, lh) unchanged -> bit-identical numerics to r11
        uint32_t ah[4][4], al[4][4];
        #pragma unroll
        for (int ms = 0; ms < 4; ++ms) {
            const int r0 = wm * 64 + ms * 16 + g;
            const float2 p0 = *reinterpret_cast<const float2*>(&As[s][r0][2 * t]);
            const float2 p1 = *reinterpret_cast<const float2*>(&As[s][r0 + 8][2 * t]);
            const float2 p2 = *reinterpret_cast<const float2*>(&As[s][r0][2 * t + 8]);
            const float2 p3 = *reinterpret_cast<const float2*>(&As[s][r0 + 8][2 * t + 8]);
            bfsplit2(p0.x, p0.y, ah[ms][0], al[ms][0]);
            bfsplit2(p1.x, p1.y, ah[ms][1], al[ms][1]);
            bfsplit2(p2.x, p2.y, ah[ms][2], al[ms][2]);
            bfsplit2(p3.x, p3.y, ah[ms][3], al[ms][3]);
        }
        #pragma unroll
        for (int ms = 0; ms < 4; ++ms)
            #pragma unroll
            for (int ns = 0; ns < 2; ++ns)
                mma16(acc[ms][ns], ah[ms], bh[ns]);   // hi*hi
        #pragma unroll
        for (int ms = 0; ms < 4; ++ms)
            #pragma unroll
            for (int ns = 0; ns < 2; ++ns)
                mma16(acc[ms][ns], ah[ms], bl[ns]);   // hi*lo
        #pragma unroll
        for (int ms = 0; ms < 4; ++ms)
            #pragma unroll
            for (int ns = 0; ns < 2; ++ns)
                mma16(acc[ms][ns], al[ms], bh[ns]);   // lo*hi
        __syncthreads();
    }

    // epilogue -> g_part[part]
    float* outp = &g_part[(size_t)part * NN * F1];
    #pragma unroll
    for (int ms = 0; ms < 4; ++ms) {
        #pragma unroll
        for (int ns = 0; ns < 2; ++ns) {
            const int col = wn * 16 + ns * 8 + 2 * t;
            const int r0  = m0 + wm * 64 + ms * 16 + g;
            if (r0 < NN) {
                float2 v0 = make_float2(acc[ms][ns][0], acc[ms][ns][1]);
                *reinterpret_cast<float2*>(&outp[(size_t)r0 * F1 + col]) = v0;
            }
            const int r1 = r0 + 8;
            if (r1 < NN) {
                float2 v1 = make_float2(acc[ms][ns][2], acc[ms][ns][3]);
                *reinterpret_cast<float2*>(&outp[(size_t)r1 * F1 + col]) = v1;
            }
        }
    }
}

// reduce split-K partials -> g_bufA, fused self-loop init -> g_bufB
__global__ void reduce_agg_kernel() {
    int idx4 = blockIdx.x * blockDim.x + threadIdx.x;
    if (idx4 < NN * F1 / 4) {
        float4 s = make_float4(0.f, 0.f, 0.f, 0.f);
        #pragma unroll
        for (int p = 0; p < SPLIT; ++p) {
            const float4 v = *reinterpret_cast<const float4*>(
                &g_part[(size_t)p * NN * F1 + (size_t)idx4 * 4]);
            s.x += v.x; s.y += v.y; s.z += v.z; s.w += v.w;
        }
        *reinterpret_cast<float4*>(&g_bufA[(size_t)idx4 * 4]) = s;
        const int row = idx4 / (F1 / 4);
        const float d  = g_dinv[row];
        const float d2 = d * d;
        float4 tt = make_float4(s.x * d2, s.y * d2, s.z * d2, s.w * d2);
        *reinterpret_cast<float4*>(&g_bufB[(size_t)idx4 * 4]) = tt;
    }
}

// ---- small GEMMs: g_bufB [NN,64] x W [64,C] -> bufA=h, bufB=h*d^2 (fused)
template <int CIN, int C>
__global__ void gemm_small_agg_kernel(const float* __restrict__ W) {
    __shared__ float w_s[CIN * C];
    for (int i = threadIdx.x; i < CIN * C; i += blockDim.x) w_s[i] = W[i];
    __syncthreads();
    const int total  = NN * C;
    const int stride = gridDim.x * blockDim.x;
    for (int idx = blockIdx.x * blockDim.x + threadIdx.x; idx < total; idx += stride) {
        const int row = idx / C;
        const int col = idx % C;
        const float* rp = &g_bufB[(size_t)row * CIN];
        float acc = 0.0f;
        #pragma unroll
        for (int k = 0; k < CIN; ++k) acc += rp[k] * w_s[k * C + col];
        g_bufA[idx] = acc;
        const float d = g_dinv[row];
        // NOTE: written AFTER the full row read above? No -- rp aliases g_bufB.
        // Safe because each thread reads only its own row, and writes below go
        // to a DIFFERENT row only when row==row (same). See launch ordering.
        g_part[idx] = acc * d * d;   // stage self-loop into g_part scratch
    }
}
// copy staged self-loop into g_bufB (separate pass: g_bufB was gemm input)
template <int C>
__global__ void selfloop_copy_kernel() {
    int idx4 = blockIdx.x * blockDim.x + threadIdx.x;
    if (idx4 < NN * C / 4) {
        const float4 v = *reinterpret_cast<const float4*>(&g_part[(size_t)idx4 * 4]);
        *reinterpret_cast<float4*>(&g_bufB[(size_t)idx4 * 4]) = v;
    }
}

// edges: one thread per (edge, 4-col group): float4 gather + red.v4
template <int C>
__global__ void agg_edges_kernel(const int* __restrict__ ei, int E) {
    constexpr int LPE = C / 4;
    const long long t = (long long)blockIdx.x * blockDim.x + threadIdx.x;
    if (t >= (long long)E * LPE) return;
    const int e = (int)(t / LPE);
    const int g = (int)(t % LPE);
    const int src = clampN(ei[e]);
    const int dst = clampN(ei[E + e]);
    const float norm = g_dinv[src] * g_dinv[dst];
    const float4 v = *reinterpret_cast<const float4*>(&g_bufA[(size_t)src * C + g * 4]);
    float* o = &g_bufB[(size_t)dst * C + g * 4];
    asm volatile("red.global.add.v4.f32 [%0], {%1, %2, %3, %4};"
                 :: "l"(o), "f"(v.x * norm), "f"(v.y * norm),
                    "f"(v.z * norm), "f"(v.w * norm)
                 : "memory");
}

// ---------------- epilogues ----------------
template <int C>
__global__ void bias_relu_kernel(const float* __restrict__ b) {
    int idx4 = blockIdx.x * blockDim.x + threadIdx.x;
    if (idx4 < NN * C / 4) {
        const float4 bb = *reinterpret_cast<const float4*>(&b[(idx4 % (C / 4)) * 4]);
        float4 v = *reinterpret_cast<float4*>(&g_bufB[(size_t)idx4 * 4]);
        v.x = fmaxf(v.x + bb.x, 0.f);
        v.y = fmaxf(v.y + bb.y, 0.f);
        v.z = fmaxf(v.z + bb.z, 0.f);
        v.w = fmaxf(v.w + bb.w, 0.f);
        *reinterpret_cast<float4*>(&g_bufB[(size_t)idx4 * 4]) = v;
    }
}

__global__ void softmax_kernel(const float* __restrict__ b, float* __restrict__ out) {
    int r = blockIdx.x * blockDim.x + threadIdx.x;
    if (r >= NN) return;
    float v[COUT];
    float m = -1e30f;
    #pragma unroll
    for (int j = 0; j < COUT; ++j) {
        v[j] = g_bufB[(size_t)r * COUT + j] + b[j];
        m = fmaxf(m, v[j]);
    }
    float s = 0.0f;
    #pragma unroll
    for (int j = 0; j < COUT; ++j) {
        v[j] = expf(v[j] - m);
        s += v[j];
    }
    const float inv = 1.0f / s;
    #pragma unroll
    for (int j = 0; j < COUT; ++j) out[(size_t)r * COUT + j] = v[j] * inv;
}

// ---------------- launch ----------------
extern "C" void kernel_launch(void* const* d_in, const int* in_sizes, int n_in,
                              void* d_out, int out_size) {
    const float* x  = (const float*)d_in[0];
    const int*   ei = (const int*)d_in[1];   // int32 (JAX x64 disabled)
    const float* W1 = (const float*)d_in[2];
    const float* b1 = (const float*)d_in[3];
    const float* W2 = (const float*)d_in[4];
    const float* b2 = (const float*)d_in[5];
    const float* W3 = (const float*)d_in[6];
    const float* b3 = (const float*)d_in[7];
    float* out = (float*)d_out;

    const int E = in_sizes[1] / 2;

    const int T = 256;
    const int gN    = (NN + T - 1) / T;
    const int gE    = (E + T - 1) / T;
    const int g64v  = (NN * F1 / 4 + T - 1) / T;
    const int g16v  = (NN * COUT / 4 + T - 1) / T;
    const int gE64  = (int)(((long long)E * (F1 / 4) + T - 1) / T);
    const int gE16  = (int)(((long long)E * (COUT / 4) + T - 1) / T);
    const dim3 gG((NN + BM - 1) / BM, SPLIT);   // 79 x 8

    // degrees + normalization + W1 prep
    deg_init_kernel<<<gN, T>>>();
    deg_count_kernel<<<gE, T>>>(ei, E);
    dinv_kernel<<<gN, T>>>();
    wfrag_kernel<<<(NCH * 256 + T - 1) / T, T>>>(W1);

    // ---- layer 1 ----
    gemm1_mma_kernel<<<gG, 256>>>(x);
    reduce_agg_kernel<<<g64v, T>>>();              // bufA = sum parts, bufB = self-loop
    agg_edges_kernel<F1><<<gE64, T>>>(ei, E);
    bias_relu_kernel<F1><<<g64v, T>>>(b1);

    // ---- layer 2 ----  (gemm writes bufA=h and stages h*d^2; copy -> bufB)
    gemm_small_agg_kernel<F1, F1><<<1480, T>>>(W2);
    selfloop_copy_kernel<F1><<<g64v, T>>>();
    agg_edges_kernel<F1><<<gE64, T>>>(ei, E);
    bias_relu_kernel<F1><<<g64v, T>>>(b2);

    // ---- layer 3 ----
    gemm_small_agg_kernel<F1, COUT><<<1480, T>>>(W3);
    selfloop_copy_kernel<COUT><<<g16v, T>>>();
    agg_edges_kernel<COUT><<<gE16, T>>>(ei, E);
    softmax_kernel<<<gN, T>>>(b3, out);
}

// round 13
// speedup vs baseline: 2.2342x; 1.0741x over previous
#include <cuda_runtime.h>
#include <cstdint>

// ---------------- problem constants (fixed-shape problem) ----------------
constexpr int NN   = 10000;  // nodes
constexpr int F1   = 64;     // hidden feat
constexpr int COUT = 16;     // classes

// GEMM1 (mma.sync bf16 m16n8k16 hi/lo) tiling
constexpr int BM    = 128;
constexpr int BK    = 16;
constexpr int SPLIT = 8;
constexpr int NCH   = NN / BK;   // 625 exact -> no K tail
constexpr int LDK   = 20;        // padded k-stride (floats)

// ---------------- device scratch (no allocation; device-code refs only) --
__device__ __align__(16) float g_deg[NN];
__device__ __align__(16) float g_dinv[NN];
__device__ __align__(16) float g_bufA[(size_t)NN * F1];
__device__ __align__(16) float g_bufB[(size_t)NN * F1];
__device__ __align__(16) float g_part[(size_t)SPLIT * NN * F1];
// B fragments: per chunk, per n8(8), per lane(32): uint4 {b0h, b1h, b0l, b1l}
__device__ __align__(16) uint4 g_wbf[(size_t)NCH * 256];

__device__ __forceinline__ int clampN(int v) {
    v = v < 0 ? 0 : v;
    return v < NN ? v : NN - 1;
}

// ---------------- PTX helpers ----------------
// pack {bf16(hiw) : upper16, bf16(low) : lower16}
__device__ __forceinline__ uint32_t packbf(float hiw, float low) {
    uint32_t r;
    asm("cvt.rn.bf16x2.f32 %0, %1, %2;" : "=r"(r) : "f"(hiw), "f"(low));
    return r;
}
// split two fp32 (e0 -> lower half, e1 -> upper half) into bf16 hi + bf16 residual
__device__ __forceinline__ void bfsplit2(float e0, float e1, uint32_t& hi, uint32_t& lo) {
    hi = packbf(e1, e0);
    const float h0 = __uint_as_float(hi << 16);
    const float h1 = __uint_as_float(hi & 0xFFFF0000u);
    lo = packbf(e1 - h1, e0 - h0);
}
__device__ __forceinline__ void mma16(float* d, const uint32_t* a, uint32_t b0, uint32_t b1) {
    asm volatile(
        "mma.sync.aligned.m16n8k16.row.col.f32.bf16.bf16.f32 "
        "{%0,%1,%2,%3},{%4,%5,%6,%7},{%8,%9},{%0,%1,%2,%3};"
        : "+f"(d[0]), "+f"(d[1]), "+f"(d[2]), "+f"(d[3])
        : "r"(a[0]), "r"(a[1]), "r"(a[2]), "r"(a[3]), "r"(b0), "r"(b1));
}
__device__ __forceinline__ void cp16(uint32_t dst, const void* src) {
    asm volatile("cp.async.cg.shared.global [%0], [%1], 16;" :: "r"(dst), "l"(src));
}

// ---------------- degree / norm ----------------
__global__ void deg_init_kernel() {
    int i = blockIdx.x * blockDim.x + threadIdx.x;
    if (i < NN) g_deg[i] = 1.0f;
}
__global__ void deg_count_kernel(const int* __restrict__ ei, int E) {
    int e = blockIdx.x * blockDim.x + threadIdx.x;
    if (e < E) atomicAdd(&g_deg[clampN(ei[E + e])], 1.0f);
}
__global__ void dinv_kernel() {
    int i = blockIdx.x * blockDim.x + threadIdx.x;
    if (i < NN) g_dinv[i] = rsqrtf(g_deg[i]);
}

// ---------------- W1 -> fragment-order packed bf16 hi/lo [verified r11] ---
__global__ void wfrag_kernel(const float* __restrict__ W) {
    int idx = blockIdx.x * blockDim.x + threadIdx.x;
    if (idx >= NCH * 256) return;
    const int lane = idx & 31;
    const int n8   = (idx >> 5) & 7;
    const int c    = idx >> 8;
    const int g = lane >> 2, t = lane & 3;
    const int n  = n8 * 8 + g;
    const int k0 = c * 16 + 2 * t;
    const float w00 = W[(size_t)k0 * 64 + n];
    const float w01 = W[(size_t)(k0 + 1) * 64 + n];
    const float w10 = W[(size_t)(k0 + 8) * 64 + n];
    const float w11 = W[(size_t)(k0 + 9) * 64 + n];
    uint32_t b0h, b0l, b1h, b1l;
    bfsplit2(w00, w01, b0h, b0l);
    bfsplit2(w10, w11, b1h, b1l);
    uint4 v;
    v.x = b0h; v.y = b1h; v.z = b0l; v.w = b1l;
    g_wbf[idx] = v;
}

// ---- GEMM1: mma.sync bf16 hi/lo, 16x64 warp tiles, split-K, term-major ---
__global__ void __launch_bounds__(256, 2) gemm1_mma_kernel(const float* __restrict__ A) {
    __shared__ __align__(16) float As[2][BM][LDK];   // raw fp32 A tiles
    __shared__ __align__(16) uint4 Bf[2][256];       // B fragments (hi/lo packed)

    const int tid  = threadIdx.x;
    const int lane = tid & 31;
    const int wid  = tid >> 5;         // warp owns rows [wid*16, wid*16+16)
    const int g    = lane >> 2;        // group id (0..7)
    const int t    = lane & 3;         // thread-in-group
    const int m0   = blockIdx.x * BM;
    const int part = blockIdx.y;

    const int q = NCH / SPLIT, r = NCH % SPLIT;
    const int cBeg = part * q + (part < r ? part : r);
    const int nCh  = q + (part < r ? 1 : 0);

    // loaders: A 512 cp16 tasks (2/thread), B 256 cp16 tasks (1/thread)
    const int am0 = tid >> 2,         aj0 = (tid & 3) * 4;
    const int am1 = (tid + 256) >> 2, aj1 = ((tid + 256) & 3) * 4;
    const float* Ap0 = A + (size_t)clampN(m0 + am0) * NN + aj0;
    const float* Ap1 = A + (size_t)clampN(m0 + am1) * NN + aj1;

    const uint32_t aDst0 = (uint32_t)__cvta_generic_to_shared(&As[0][am0][aj0]);
    const uint32_t aDst1 = (uint32_t)__cvta_generic_to_shared(&As[0][am1][aj1]);
    const uint32_t bDst  = (uint32_t)__cvta_generic_to_shared(&Bf[0][0]);
    const uint32_t stageA = (uint32_t)(BM * LDK * 4);
    const uint32_t stageB = 4096u;

    float acc[8][4] = {};   // [n8][reg]

    // prologue: chunk cBeg -> stage 0
    {
        const size_t kf = (size_t)cBeg * BK;
        cp16(aDst0, Ap0 + kf);
        cp16(aDst1, Ap1 + kf);
        cp16(bDst + (uint32_t)tid * 16, &g_wbf[(size_t)cBeg * 256 + tid]);
        asm volatile("cp.async.commit_group;");
    }

    for (int i = 0; i < nCh; ++i) {
        const int s = i & 1;
        if (i + 1 < nCh) {
            const uint32_t ns = (uint32_t)(s ^ 1);
            const size_t kf = (size_t)(cBeg + i + 1) * BK;
            cp16(aDst0 + ns * stageA, Ap0 + kf);
            cp16(aDst1 + ns * stageA, Ap1 + kf);
            cp16(bDst + ns * stageB + (uint32_t)tid * 16,
                 &g_wbf[(size_t)(cBeg + i + 1) * 256 + tid]);
            asm volatile("cp.async.commit_group;");
            asm volatile("cp.async.wait_group 1;");
        } else {
            asm volatile("cp.async.wait_group 0;");
        }
        __syncthreads();

        // B fragments: all 8 n-strips, resident in registers
        uint4 bv[8];
        #pragma unroll
        for (int n8 = 0; n8 < 8; ++n8)
            bv[n8] = Bf[s][n8 * 32 + lane];

        // A fragment: loaded + split exactly once (owning warp only)
        const int r0 = wid * 16 + g;
        const float2 p0 = *reinterpret_cast<const float2*>(&As[s][r0][2 * t]);
        const float2 p1 = *reinterpret_cast<const float2*>(&As[s][r0 + 8][2 * t]);
        const float2 p2 = *reinterpret_cast<const float2*>(&As[s][r0][2 * t + 8]);
        const float2 p3 = *reinterpret_cast<const float2*>(&As[s][r0 + 8][2 * t + 8]);
        uint32_t ah[4], al[4];
        bfsplit2(p0.x, p0.y, ah[0], al[0]);
        bfsplit2(p1.x, p1.y, ah[1], al[1]);
        bfsplit2(p2.x, p2.y, ah[2], al[2]);
        bfsplit2(p3.x, p3.y, ah[3], al[3]);

        // term-major passes; per-accumulator term order (hh, hl, lh) == r12
        #pragma unroll
        for (int n8 = 0; n8 < 8; ++n8)
            mma16(acc[n8], ah, bv[n8].x, bv[n8].y);   // hi*hi
        #pragma unroll
        for (int n8 = 0; n8 < 8; ++n8)
            mma16(acc[n8], ah, bv[n8].z, bv[n8].w);   // hi*lo
        #pragma unroll
        for (int n8 = 0; n8 < 8; ++n8)
            mma16(acc[n8], al, bv[n8].x, bv[n8].y);   // lo*hi
        __syncthreads();
    }

    // epilogue -> g_part[part]
    float* outp = &g_part[(size_t)part * NN * F1];
    const int r0g = m0 + wid * 16 + g;
    const int r1g = r0g + 8;
    #pragma unroll
    for (int n8 = 0; n8 < 8; ++n8) {
        const int col = n8 * 8 + 2 * t;
        if (r0g < NN) {
            float2 v0 = make_float2(acc[n8][0], acc[n8][1]);
            *reinterpret_cast<float2*>(&outp[(size_t)r0g * F1 + col]) = v0;
        }
        if (r1g < NN) {
            float2 v1 = make_float2(acc[n8][2], acc[n8][3]);
            *reinterpret_cast<float2*>(&outp[(size_t)r1g * F1 + col]) = v1;
        }
    }
}

// reduce split-K partials -> g_bufA, fused self-loop init -> g_bufB
__global__ void reduce_agg_kernel() {
    int idx4 = blockIdx.x * blockDim.x + threadIdx.x;
    if (idx4 < NN * F1 / 4) {
        float4 s = make_float4(0.f, 0.f, 0.f, 0.f);
        #pragma unroll
        for (int p = 0; p < SPLIT; ++p) {
            const float4 v = *reinterpret_cast<const float4*>(
                &g_part[(size_t)p * NN * F1 + (size_t)idx4 * 4]);
            s.x += v.x; s.y += v.y; s.z += v.z; s.w += v.w;
        }
        *reinterpret_cast<float4*>(&g_bufA[(size_t)idx4 * 4]) = s;
        const int row = idx4 / (F1 / 4);
        const float d  = g_dinv[row];
        const float d2 = d * d;
        float4 tt = make_float4(s.x * d2, s.y * d2, s.z * d2, s.w * d2);
        *reinterpret_cast<float4*>(&g_bufB[(size_t)idx4 * 4]) = tt;
    }
}

// ---- small GEMMs: g_bufB [NN,64] x W [64,C] -> bufA=h, stage h*d^2 -------
template <int CIN, int C>
__global__ void gemm_small_agg_kernel(const float* __restrict__ W) {
    __shared__ float w_s[CIN * C];
    for (int i = threadIdx.x; i < CIN * C; i += blockDim.x) w_s[i] = W[i];
    __syncthreads();
    const int total  = NN * C;
    const int stride = gridDim.x * blockDim.x;
    for (int idx = blockIdx.x * blockDim.x + threadIdx.x; idx < total; idx += stride) {
        const int row = idx / C;
        const int col = idx % C;
        const float* rp = &g_bufB[(size_t)row * CIN];
        float acc = 0.0f;
        #pragma unroll
        for (int k = 0; k < CIN; ++k) acc += rp[k] * w_s[k * C + col];
        g_bufA[idx] = acc;
        const float d = g_dinv[row];
        g_part[idx] = acc * d * d;   // stage self-loop into g_part scratch
    }
}
// copy staged self-loop into g_bufB (separate pass: g_bufB was gemm input)
template <int C>
__global__ void selfloop_copy_kernel() {
    int idx4 = blockIdx.x * blockDim.x + threadIdx.x;
    if (idx4 < NN * C / 4) {
        const float4 v = *reinterpret_cast<const float4*>(&g_part[(size_t)idx4 * 4]);
        *reinterpret_cast<float4*>(&g_bufB[(size_t)idx4 * 4]) = v;
    }
}

// edges: one thread per (edge, 4-col group): float4 gather + red.v4
template <int C>
__global__ void agg_edges_kernel(const int* __restrict__ ei, int E) {
    constexpr int LPE = C / 4;
    const long long t = (long long)blockIdx.x * blockDim.x + threadIdx.x;
    if (t >= (long long)E * LPE) return;
    const int e = (int)(t / LPE);
    const int g = (int)(t % LPE);
    const int src = clampN(ei[e]);
    const int dst = clampN(ei[E + e]);
    const float norm = g_dinv[src] * g_dinv[dst];
    const float4 v = *reinterpret_cast<const float4*>(&g_bufA[(size_t)src * C + g * 4]);
    float* o = &g_bufB[(size_t)dst * C + g * 4];
    asm volatile("red.global.add.v4.f32 [%0], {%1, %2, %3, %4};"
                 :: "l"(o), "f"(v.x * norm), "f"(v.y * norm),
                    "f"(v.z * norm), "f"(v.w * norm)
                 : "memory");
}

// ---------------- epilogues ----------------
template <int C>
__global__ void bias_relu_kernel(const float* __restrict__ b) {
    int idx4 = blockIdx.x * blockDim.x + threadIdx.x;
    if (idx4 < NN * C / 4) {
        const float4 bb = *reinterpret_cast<const float4*>(&b[(idx4 % (C / 4)) * 4]);
        float4 v = *reinterpret_cast<float4*>(&g_bufB[(size_t)idx4 * 4]);
        v.x = fmaxf(v.x + bb.x, 0.f);
        v.y = fmaxf(v.y + bb.y, 0.f);
        v.z = fmaxf(v.z + bb.z, 0.f);
        v.w = fmaxf(v.w + bb.w, 0.f);
        *reinterpret_cast<float4*>(&g_bufB[(size_t)idx4 * 4]) = v;
    }
}

__global__ void softmax_kernel(const float* __restrict__ b, float* __restrict__ out) {
    int r = blockIdx.x * blockDim.x + threadIdx.x;
    if (r >= NN) return;
    float v[COUT];
    float m = -1e30f;
    #pragma unroll
    for (int j = 0; j < COUT; ++j) {
        v[j] = g_bufB[(size_t)r * COUT + j] + b[j];
        m = fmaxf(m, v[j]);
    }
    float s = 0.0f;
    #pragma unroll
    for (int j = 0; j < COUT; ++j) {
        v[j] = expf(v[j] - m);
        s += v[j];
    }
    const float inv = 1.0f / s;
    #pragma unroll
    for (int j = 0; j < COUT; ++j) out[(size_t)r * COUT + j] = v[j] * inv;
}

// ---------------- launch ----------------
extern "C" void kernel_launch(void* const* d_in, const int* in_sizes, int n_in,
                              void* d_out, int out_size) {
    const float* x  = (const float*)d_in[0];
    const int*   ei = (const int*)d_in[1];   // int32 (JAX x64 disabled)
    const float* W1 = (const float*)d_in[2];
    const float* b1 = (const float*)d_in[3];
    const float* W2 = (const float*)d_in[4];
    const float* b2 = (const float*)d_in[5];
    const float* W3 = (const float*)d_in[6];
    const float* b3 = (const float*)d_in[7];
    float* out = (float*)d_out;

    const int E = in_sizes[1] / 2;

    const int T = 256;
    const int gN    = (NN + T - 1) / T;
    const int gE    = (E + T - 1) / T;
    const int g64v  = (NN * F1 / 4 + T - 1) / T;
    const int g16v  = (NN * COUT / 4 + T - 1) / T;
    const int gE64  = (int)(((long long)E * (F1 / 4) + T - 1) / T);
    const int gE16  = (int)(((long long)E * (COUT / 4) + T - 1) / T);
    const dim3 gG((NN + BM - 1) / BM, SPLIT);   // 79 x 8

    // degrees + normalization + W1 prep
    deg_init_kernel<<<gN, T>>>();
    deg_count_kernel<<<gE, T>>>(ei, E);
    dinv_kernel<<<gN, T>>>();
    wfrag_kernel<<<(NCH * 256 + T - 1) / T, T>>>(W1);

    // ---- layer 1 ----
    gemm1_mma_kernel<<<gG, 256>>>(x);
    reduce_agg_kernel<<<g64v, T>>>();              // bufA = sum parts, bufB = self-loop
    agg_edges_kernel<F1><<<gE64, T>>>(ei, E);
    bias_relu_kernel<F1><<<g64v, T>>>(b1);

    // ---- layer 2 ----  (gemm writes bufA=h and stages h*d^2; copy -> bufB)
    gemm_small_agg_kernel<F1, F1><<<1480, T>>>(W2);
    selfloop_copy_kernel<F1><<<g64v, T>>>();
    agg_edges_kernel<F1><<<gE64, T>>>(ei, E);
    bias_relu_kernel<F1><<<g64v, T>>>(b2);

    // ---- layer 3 ----
    gemm_small_agg_kernel<F1, COUT><<<1480, T>>>(W3);
    selfloop_copy_kernel<COUT><<<g16v, T>>>();
    agg_edges_kernel<COUT><<<gE16, T>>>(ei, E);
    softmax_kernel<<<gN, T>>>(b3, out);
}

// round 14
// speedup vs baseline: 2.4119x; 1.0795x over previous
#include <cuda_runtime.h>
#include <cstdint>

// ---------------- problem constants (fixed-shape problem) ----------------
constexpr int NN    = 10000;  // nodes
constexpr int F1    = 64;     // hidden feat
constexpr int COUT  = 16;     // classes
constexpr int E_MAX = 320000;

// GEMM1 (mma.sync bf16 m16n8k16 hi/lo) tiling
constexpr int BM    = 128;
constexpr int BK    = 16;
constexpr int SPLIT = 16;
constexpr int NCH   = NN / BK;   // 625 exact -> no K tail
constexpr int LDK   = 20;        // padded k-stride (floats)

// ---------------- device scratch (no allocation; device-code refs only) --
__device__ __align__(16) int   g_cnt[NN];      // in-degree (excl self)
__device__ __align__(16) int   g_fill[NN];
__device__ __align__(16) int   g_ptr[NN + 1];
__device__ __align__(16) int   g_csrc[E_MAX];
__device__ __align__(16) float g_dinv[NN];
__device__ __align__(16) float g_bufA[(size_t)NN * F1];
__device__ __align__(16) float g_bufB[(size_t)NN * F1];
__device__ __align__(16) float g_part[(size_t)SPLIT * NN * F1];
// B fragments: per chunk, per n8(8), per lane(32): uint4 {b0h, b1h, b0l, b1l}
__device__ __align__(16) uint4 g_wbf[(size_t)NCH * 256];

__device__ __forceinline__ int clampN(int v) {
    v = v < 0 ? 0 : v;
    return v < NN ? v : NN - 1;
}

// ---------------- PTX helpers ----------------
__device__ __forceinline__ uint32_t packbf(float hiw, float low) {
    uint32_t r;
    asm("cvt.rn.bf16x2.f32 %0, %1, %2;" : "=r"(r) : "f"(hiw), "f"(low));
    return r;
}
__device__ __forceinline__ void bfsplit2(float e0, float e1, uint32_t& hi, uint32_t& lo) {
    hi = packbf(e1, e0);
    const float h0 = __uint_as_float(hi << 16);
    const float h1 = __uint_as_float(hi & 0xFFFF0000u);
    lo = packbf(e1 - h1, e0 - h0);
}
__device__ __forceinline__ void mma16(float* d, const uint32_t* a, uint32_t b0, uint32_t b1) {
    asm volatile(
        "mma.sync.aligned.m16n8k16.row.col.f32.bf16.bf16.f32 "
        "{%0,%1,%2,%3},{%4,%5,%6,%7},{%8,%9},{%0,%1,%2,%3};"
        : "+f"(d[0]), "+f"(d[1]), "+f"(d[2]), "+f"(d[3])
        : "r"(a[0]), "r"(a[1]), "r"(a[2]), "r"(a[3]), "r"(b0), "r"(b1));
}
__device__ __forceinline__ void cp16(uint32_t dst, const void* src) {
    asm volatile("cp.async.cg.shared.global [%0], [%1], 16;" :: "r"(dst), "l"(src));
}

// ---------------- degree / CSR build ----------------
__global__ void deg_init_kernel() {
    int i = blockIdx.x * blockDim.x + threadIdx.x;
    if (i < NN) { g_cnt[i] = 0; g_fill[i] = 0; }
}
__global__ void deg_count_kernel(const int* __restrict__ ei, int E) {
    int e = blockIdx.x * blockDim.x + threadIdx.x;
    if (e < E) atomicAdd(&g_cnt[clampN(ei[E + e])], 1);
}
__global__ void dinv_kernel() {
    int i = blockIdx.x * blockDim.x + threadIdx.x;
    if (i < NN) g_dinv[i] = rsqrtf(1.0f + (float)g_cnt[i]);
}
// exclusive prefix scan of g_cnt -> g_ptr (single block, 1024 threads)
__global__ void csr_scan_kernel() {
    __shared__ int ssum[1024];
    const int tid = threadIdx.x;
    constexpr int PER = (NN + 1023) / 1024;  // 10
    const int base = tid * PER;
    int local[PER];
    int s = 0;
    #pragma unroll
    for (int i = 0; i < PER; ++i) {
        const int idx = base + i;
        const int v = (idx < NN) ? g_cnt[idx] : 0;
        local[i] = s;
        s += v;
    }
    ssum[tid] = s;
    __syncthreads();
    for (int off = 1; off < 1024; off <<= 1) {
        const int v = (tid >= off) ? ssum[tid - off] : 0;
        __syncthreads();
        ssum[tid] += v;
        __syncthreads();
    }
    const int tbase = (tid == 0) ? 0 : ssum[tid - 1];
    #pragma unroll
    for (int i = 0; i < PER; ++i) {
        const int idx = base + i;
        if (idx < NN) g_ptr[idx] = tbase + local[i];
    }
    if (tid == 1023) g_ptr[NN] = ssum[1023];
}
__global__ void csr_scatter_kernel(const int* __restrict__ ei, int E) {
    int e = blockIdx.x * blockDim.x + threadIdx.x;
    if (e < E) {
        const int src = clampN(ei[e]);
        const int dst = clampN(ei[E + e]);
        int pos = g_ptr[dst] + atomicAdd(&g_fill[dst], 1);
        pos = pos < E_MAX ? (pos < 0 ? 0 : pos) : E_MAX - 1;
        g_csrc[pos] = src;
    }
}

// ---------------- W1 -> fragment-order packed bf16 hi/lo [verified r11] ---
__global__ void wfrag_kernel(const float* __restrict__ W) {
    int idx = blockIdx.x * blockDim.x + threadIdx.x;
    if (idx >= NCH * 256) return;
    const int lane = idx & 31;
    const int n8   = (idx >> 5) & 7;
    const int c    = idx >> 8;
    const int g = lane >> 2, t = lane & 3;
    const int n  = n8 * 8 + g;
    const int k0 = c * 16 + 2 * t;
    const float w00 = W[(size_t)k0 * 64 + n];
    const float w01 = W[(size_t)(k0 + 1) * 64 + n];
    const float w10 = W[(size_t)(k0 + 8) * 64 + n];
    const float w11 = W[(size_t)(k0 + 9) * 64 + n];
    uint32_t b0h, b0l, b1h, b1l;
    bfsplit2(w00, w01, b0h, b0l);
    bfsplit2(w10, w11, b1h, b1l);
    uint4 v;
    v.x = b0h; v.y = b1h; v.z = b0l; v.w = b1l;
    g_wbf[idx] = v;
}

// ---- GEMM1: mma.sync bf16 hi/lo, 16x64 warp tiles, split-K [r13 core] ----
__global__ void __launch_bounds__(256, 2) gemm1_mma_kernel(const float* __restrict__ A) {
    __shared__ __align__(16) float As[2][BM][LDK];   // raw fp32 A tiles
    __shared__ __align__(16) uint4 Bf[2][256];       // B fragments (hi/lo packed)

    const int tid  = threadIdx.x;
    const int lane = tid & 31;
    const int wid  = tid >> 5;         // warp owns rows [wid*16, wid*16+16)
    const int g    = lane >> 2;
    const int t    = lane & 3;
    const int m0   = blockIdx.x * BM;
    const int part = blockIdx.y;

    const int q = NCH / SPLIT, r = NCH % SPLIT;
    const int cBeg = part * q + (part < r ? part : r);
    const int nCh  = q + (part < r ? 1 : 0);

    const int am0 = tid >> 2,         aj0 = (tid & 3) * 4;
    const int am1 = (tid + 256) >> 2, aj1 = ((tid + 256) & 3) * 4;
    const float* Ap0 = A + (size_t)clampN(m0 + am0) * NN + aj0;
    const float* Ap1 = A + (size_t)clampN(m0 + am1) * NN + aj1;

    const uint32_t aDst0 = (uint32_t)__cvta_generic_to_shared(&As[0][am0][aj0]);
    const uint32_t aDst1 = (uint32_t)__cvta_generic_to_shared(&As[0][am1][aj1]);
    const uint32_t bDst  = (uint32_t)__cvta_generic_to_shared(&Bf[0][0]);
    const uint32_t stageA = (uint32_t)(BM * LDK * 4);
    const uint32_t stageB = 4096u;

    float acc[8][4] = {};   // [n8][reg]

    {
        const size_t kf = (size_t)cBeg * BK;
        cp16(aDst0, Ap0 + kf);
        cp16(aDst1, Ap1 + kf);
        cp16(bDst + (uint32_t)tid * 16, &g_wbf[(size_t)cBeg * 256 + tid]);
        asm volatile("cp.async.commit_group;");
    }

    for (int i = 0; i < nCh; ++i) {
        const int s = i & 1;
        if (i + 1 < nCh) {
            const uint32_t ns = (uint32_t)(s ^ 1);
            const size_t kf = (size_t)(cBeg + i + 1) * BK;
            cp16(aDst0 + ns * stageA, Ap0 + kf);
            cp16(aDst1 + ns * stageA, Ap1 + kf);
            cp16(bDst + ns * stageB + (uint32_t)tid * 16,
                 &g_wbf[(size_t)(cBeg + i + 1) * 256 + tid]);
            asm volatile("cp.async.commit_group;");
            asm volatile("cp.async.wait_group 1;");
        } else {
            asm volatile("cp.async.wait_group 0;");
        }
        __syncthreads();

        uint4 bv[8];
        #pragma unroll
        for (int n8 = 0; n8 < 8; ++n8)
            bv[n8] = Bf[s][n8 * 32 + lane];

        const int r0 = wid * 16 + g;
        const float2 p0 = *reinterpret_cast<const float2*>(&As[s][r0][2 * t]);
        const float2 p1 = *reinterpret_cast<const float2*>(&As[s][r0 + 8][2 * t]);
        const float2 p2 = *reinterpret_cast<const float2*>(&As[s][r0][2 * t + 8]);
        const float2 p3 = *reinterpret_cast<const float2*>(&As[s][r0 + 8][2 * t + 8]);
        uint32_t ah[4], al[4];
        bfsplit2(p0.x, p0.y, ah[0], al[0]);
        bfsplit2(p1.x, p1.y, ah[1], al[1]);
        bfsplit2(p2.x, p2.y, ah[2], al[2]);
        bfsplit2(p3.x, p3.y, ah[3], al[3]);

        #pragma unroll
        for (int n8 = 0; n8 < 8; ++n8)
            mma16(acc[n8], ah, bv[n8].x, bv[n8].y);   // hi*hi
        #pragma unroll
        for (int n8 = 0; n8 < 8; ++n8)
            mma16(acc[n8], ah, bv[n8].z, bv[n8].w);   // hi*lo
        #pragma unroll
        for (int n8 = 0; n8 < 8; ++n8)
            mma16(acc[n8], al, bv[n8].x, bv[n8].y);   // lo*hi
        __syncthreads();
    }

    float* outp = &g_part[(size_t)part * NN * F1];
    const int r0g = m0 + wid * 16 + g;
    const int r1g = r0g + 8;
    #pragma unroll
    for (int n8 = 0; n8 < 8; ++n8) {
        const int col = n8 * 8 + 2 * t;
        if (r0g < NN) {
            float2 v0 = make_float2(acc[n8][0], acc[n8][1]);
            *reinterpret_cast<float2*>(&outp[(size_t)r0g * F1 + col]) = v0;
        }
        if (r1g < NN) {
            float2 v1 = make_float2(acc[n8][2], acc[n8][3]);
            *reinterpret_cast<float2*>(&outp[(size_t)r1g * F1 + col]) = v1;
        }
    }
}

// reduce split-K partials -> g_bufA
__global__ void reduce_part_kernel() {
    int idx4 = blockIdx.x * blockDim.x + threadIdx.x;
    if (idx4 < NN * F1 / 4) {
        float4 s = make_float4(0.f, 0.f, 0.f, 0.f);
        #pragma unroll
        for (int p = 0; p < SPLIT; ++p) {
            const float4 v = *reinterpret_cast<const float4*>(
                &g_part[(size_t)p * NN * F1 + (size_t)idx4 * 4]);
            s.x += v.x; s.y += v.y; s.z += v.z; s.w += v.w;
        }
        *reinterpret_cast<float4*>(&g_bufA[(size_t)idx4 * 4]) = s;
    }
}

// ---- small GEMMs: g_bufB [NN,64] x W [64,C] -> g_bufA --------------------
template <int CIN, int C>
__global__ void gemm_small_kernel(const float* __restrict__ W) {
    __shared__ float w_s[CIN * C];
    for (int i = threadIdx.x; i < CIN * C; i += blockDim.x) w_s[i] = W[i];
    __syncthreads();
    const int total  = NN * C;
    const int stride = gridDim.x * blockDim.x;
    for (int idx = blockIdx.x * blockDim.x + threadIdx.x; idx < total; idx += stride) {
        const int row = idx / C;
        const int col = idx % C;
        const float* rp = &g_bufB[(size_t)row * CIN];
        float acc = 0.0f;
        #pragma unroll
        for (int k = 0; k < CIN; ++k) acc += rp[k] * w_s[k * C + col];
        g_bufA[idx] = acc;
    }
}

// ---- CSR pull aggregation: bufB[dst] = selfloop + sum edges (+bias,relu) --
// one warp per dst; lane handles 2 columns (C/2 active lanes)
template <int C, bool BIAS_RELU>
__global__ void agg_csr_kernel(const float* __restrict__ bias) {
    const int w    = (blockIdx.x * blockDim.x + threadIdx.x) >> 5;
    const int lane = threadIdx.x & 31;
    if (w >= NN) return;
    constexpr int L = C / 2;
    const int dst = w;
    const float dd = g_dinv[dst];
    const int p0 = g_ptr[dst];
    const int p1 = g_ptr[dst + 1];

    float2 acc = make_float2(0.f, 0.f);
    if (lane < L) {
        const float2 v = *reinterpret_cast<const float2*>(&g_bufA[(size_t)dst * C + lane * 2]);
        acc.x = v.x * dd * dd;
        acc.y = v.y * dd * dd;
    }
    int j = p0;
    for (; j + 1 < p1; j += 2) {   // 2-way unroll for MLP
        const int s0 = g_csrc[j];
        const int s1 = g_csrc[j + 1];
        const float n0 = g_dinv[s0] * dd;
        const float n1 = g_dinv[s1] * dd;
        if (lane < L) {
            const float2 v0 = *reinterpret_cast<const float2*>(&g_bufA[(size_t)s0 * C + lane * 2]);
            const float2 v1 = *reinterpret_cast<const float2*>(&g_bufA[(size_t)s1 * C + lane * 2]);
            acc.x += v0.x * n0; acc.y += v0.y * n0;
            acc.x += v1.x * n1; acc.y += v1.y * n1;
        }
    }
    if (j < p1) {
        const int s0 = g_csrc[j];
        const float n0 = g_dinv[s0] * dd;
        if (lane < L) {
            const float2 v0 = *reinterpret_cast<const float2*>(&g_bufA[(size_t)s0 * C + lane * 2]);
            acc.x += v0.x * n0; acc.y += v0.y * n0;
        }
    }
    if (lane < L) {
        if (BIAS_RELU) {
            const float2 bb = *reinterpret_cast<const float2*>(&bias[lane * 2]);
            acc.x = fmaxf(acc.x + bb.x, 0.f);
            acc.y = fmaxf(acc.y + bb.y, 0.f);
        }
        *reinterpret_cast<float2*>(&g_bufB[(size_t)dst * C + lane * 2]) = acc;
    }
}

// ---------------- softmax (adds bias b3) ----------------
__global__ void softmax_kernel(const float* __restrict__ b, float* __restrict__ out) {
    int r = blockIdx.x * blockDim.x + threadIdx.x;
    if (r >= NN) return;
    float v[COUT];
    float m = -1e30f;
    #pragma unroll
    for (int j = 0; j < COUT; ++j) {
        v[j] = g_bufB[(size_t)r * COUT + j] + b[j];
        m = fmaxf(m, v[j]);
    }
    float s = 0.0f;
    #pragma unroll
    for (int j = 0; j < COUT; ++j) {
        v[j] = expf(v[j] - m);
        s += v[j];
    }
    const float inv = 1.0f / s;
    #pragma unroll
    for (int j = 0; j < COUT; ++j) out[(size_t)r * COUT + j] = v[j] * inv;
}

// ---------------- launch ----------------
extern "C" void kernel_launch(void* const* d_in, const int* in_sizes, int n_in,
                              void* d_out, int out_size) {
    const float* x  = (const float*)d_in[0];
    const int*   ei = (const int*)d_in[1];   // int32 (JAX x64 disabled)
    const float* W1 = (const float*)d_in[2];
    const float* b1 = (const float*)d_in[3];
    const float* W2 = (const float*)d_in[4];
    const float* b2 = (const float*)d_in[5];
    const float* W3 = (const float*)d_in[6];
    const float* b3 = (const float*)d_in[7];
    float* out = (float*)d_out;

    int E = in_sizes[1] / 2;
    if (E > E_MAX) E = E_MAX;

    const int T = 256;
    const int gN    = (NN + T - 1) / T;
    const int gE    = (E + T - 1) / T;
    const int g64v  = (NN * F1 / 4 + T - 1) / T;
    const int gWarp = (NN * 32 + T - 1) / T;      // one warp per node
    const dim3 gG((NN + BM - 1) / BM, SPLIT);     // 79 x 16

    // degree + CSR + norm + W1 prep
    deg_init_kernel<<<gN, T>>>();
    deg_count_kernel<<<gE, T>>>(ei, E);
    dinv_kernel<<<gN, T>>>();
    csr_scan_kernel<<<1, 1024>>>();
    csr_scatter_kernel<<<gE, T>>>(ei, E);
    wfrag_kernel<<<(NCH * 256 + T - 1) / T, T>>>(W1);

    // ---- layer 1 ----
    gemm1_mma_kernel<<<gG, 256>>>(x);
    reduce_part_kernel<<<g64v, T>>>();                  // bufA = sum parts
    agg_csr_kernel<F1, true><<<gWarp, T>>>(b1);         // bufB = relu(agg + b1)

    // ---- layer 2 ----
    gemm_small_kernel<F1, F1><<<1480, T>>>(W2);         // bufA = bufB @ W2
    agg_csr_kernel<F1, true><<<gWarp, T>>>(b2);

    // ---- layer 3 ----
    gemm_small_kernel<F1, COUT><<<1480, T>>>(W3);
    agg_csr_kernel<COUT, false><<<gWarp, T>>>(nullptr);
    softmax_kernel<<<gN, T>>>(b3, out);
}

// round 15
// speedup vs baseline: 2.6648x; 1.1049x over previous
#include <cuda_runtime.h>
#include <cstdint>

// ---------------- problem constants (fixed-shape problem) ----------------
constexpr int NN    = 10000;  // nodes
constexpr int F1    = 64;     // hidden feat
constexpr int COUT  = 16;     // classes
constexpr int E_MAX = 320000;

// GEMM1 (mma.sync bf16 m16n8k16 hi/lo) tiling
constexpr int BM     = 128;
constexpr int BK     = 16;
constexpr int SPLIT  = 16;
constexpr int NCH    = NN / BK;   // 625 exact
constexpr int LDK    = 20;        // padded k-stride (floats)
constexpr int STAGES = 4;

// ---------------- device scratch (no allocation; device-code refs only) --
__device__ __align__(16) int   g_cnt[NN];
__device__ __align__(16) int   g_fill[NN];
__device__ __align__(16) int   g_ptr[NN + 1];
__device__ __align__(16) int   g_csrc[E_MAX];
__device__ __align__(16) float g_dinv[NN];
__device__ __align__(16) float g_bufA[(size_t)NN * F1];
__device__ __align__(16) float g_bufB[(size_t)NN * F1];
__device__ __align__(16) float g_part[(size_t)SPLIT * NN * F1];
__device__ __align__(16) uint4 g_wbf[(size_t)NCH * 256];

__device__ __forceinline__ int clampN(int v) {
    v = v < 0 ? 0 : v;
    return v < NN ? v : NN - 1;
}

// ---------------- PTX helpers ----------------
__device__ __forceinline__ uint32_t packbf(float hiw, float low) {
    uint32_t r;
    asm("cvt.rn.bf16x2.f32 %0, %1, %2;" : "=r"(r) : "f"(hiw), "f"(low));
    return r;
}
__device__ __forceinline__ void bfsplit2(float e0, float e1, uint32_t& hi, uint32_t& lo) {
    hi = packbf(e1, e0);
    const float h0 = __uint_as_float(hi << 16);
    const float h1 = __uint_as_float(hi & 0xFFFF0000u);
    lo = packbf(e1 - h1, e0 - h0);
}
__device__ __forceinline__ void mma16(float* d, const uint32_t* a, uint32_t b0, uint32_t b1) {
    asm volatile(
        "mma.sync.aligned.m16n8k16.row.col.f32.bf16.bf16.f32 "
        "{%0,%1,%2,%3},{%4,%5,%6,%7},{%8,%9},{%0,%1,%2,%3};"
        : "+f"(d[0]), "+f"(d[1]), "+f"(d[2]), "+f"(d[3])
        : "r"(a[0]), "r"(a[1]), "r"(a[2]), "r"(a[3]), "r"(b0), "r"(b1));
}
__device__ __forceinline__ void cp16(uint32_t dst, const void* src) {
    asm volatile("cp.async.cg.shared.global [%0], [%1], 16;" :: "r"(dst), "l"(src));
}

// ---------------- degree / CSR build ----------------
__global__ void deg_init_kernel() {
    int i = blockIdx.x * blockDim.x + threadIdx.x;
    if (i < NN) { g_cnt[i] = 0; g_fill[i] = 0; }
}
__global__ void deg_count_kernel(const int* __restrict__ ei, int E) {
    int e = blockIdx.x * blockDim.x + threadIdx.x;
    if (e < E) atomicAdd(&g_cnt[clampN(ei[E + e])], 1);
}
__global__ void dinv_kernel() {
    int i = blockIdx.x * blockDim.x + threadIdx.x;
    if (i < NN) g_dinv[i] = rsqrtf(1.0f + (float)g_cnt[i]);
}
// exclusive prefix scan of g_cnt -> g_ptr (1024 threads, shuffle two-level)
__global__ void csr_scan_kernel() {
    __shared__ int wsum[32];
    __shared__ int woff[32];
    const int tid  = threadIdx.x;
    const int lane = tid & 31;
    const int wid  = tid >> 5;
    constexpr int PER = (NN + 1023) / 1024;  // 10
    const int base = tid * PER;
    int local[PER];
    int tsum = 0;
    #pragma unroll
    for (int i = 0; i < PER; ++i) {
        const int idx = base + i;
        const int v = (idx < NN) ? g_cnt[idx] : 0;
        local[i] = tsum;
        tsum += v;
    }
    // inclusive warp scan of tsum
    int inc = tsum;
    #pragma unroll
    for (int o = 1; o < 32; o <<= 1) {
        const int v = __shfl_up_sync(0xFFFFFFFFu, inc, o);
        if (lane >= o) inc += v;
    }
    if (lane == 31) wsum[wid] = inc;
    __syncthreads();
    if (wid == 0) {
        int v = wsum[lane];
        int inc2 = v;
        #pragma unroll
        for (int o = 1; o < 32; o <<= 1) {
            const int u = __shfl_up_sync(0xFFFFFFFFu, inc2, o);
            if (lane >= o) inc2 += u;
        }
        woff[lane] = inc2 - v;   // exclusive warp offsets
    }
    __syncthreads();
    const int tbase = woff[wid] + (inc - tsum);
    #pragma unroll
    for (int i = 0; i < PER; ++i) {
        const int idx = base + i;
        if (idx < NN) g_ptr[idx] = tbase + local[i];
    }
    if (tid == 1023) g_ptr[NN] = tbase + tsum;
}
__global__ void csr_scatter_kernel(const int* __restrict__ ei, int E) {
    int e = blockIdx.x * blockDim.x + threadIdx.x;
    if (e < E) {
        const int src = clampN(ei[e]);
        const int dst = clampN(ei[E + e]);
        int pos = g_ptr[dst] + atomicAdd(&g_fill[dst], 1);
        pos = pos < E_MAX ? (pos < 0 ? 0 : pos) : E_MAX - 1;
        g_csrc[pos] = src;
    }
}

// ---------------- W1 -> fragment-order packed bf16 hi/lo [verified r11] ---
__global__ void wfrag_kernel(const float* __restrict__ W) {
    int idx = blockIdx.x * blockDim.x + threadIdx.x;
    if (idx >= NCH * 256) return;
    const int lane = idx & 31;
    const int n8   = (idx >> 5) & 7;
    const int c    = idx >> 8;
    const int g = lane >> 2, t = lane & 3;
    const int n  = n8 * 8 + g;
    const int k0 = c * 16 + 2 * t;
    const float w00 = W[(size_t)k0 * 64 + n];
    const float w01 = W[(size_t)(k0 + 1) * 64 + n];
    const float w10 = W[(size_t)(k0 + 8) * 64 + n];
    const float w11 = W[(size_t)(k0 + 9) * 64 + n];
    uint32_t b0h, b0l, b1h, b1l;
    bfsplit2(w00, w01, b0h, b0l);
    bfsplit2(w10, w11, b1h, b1l);
    uint4 v;
    v.x = b0h; v.y = b1h; v.z = b0l; v.w = b1l;
    g_wbf[idx] = v;
}

// ---- GEMM1: bf16 hi/lo, 16x64 warp tiles, split-K, 4-stage pipeline -----
__global__ void __launch_bounds__(256, 2) gemm1_mma_kernel(const float* __restrict__ A) {
    __shared__ __align__(16) float As[STAGES][BM][LDK];   // 40960 B
    __shared__ __align__(16) uint4 Bf[STAGES][256];       // 16384 B

    const int tid  = threadIdx.x;
    const int lane = tid & 31;
    const int wid  = tid >> 5;
    const int g    = lane >> 2;
    const int t    = lane & 3;
    const int m0   = blockIdx.x * BM;
    const int part = blockIdx.y;

    const int q = NCH / SPLIT, r = NCH % SPLIT;
    const int cBeg = part * q + (part < r ? part : r);
    const int nCh  = q + (part < r ? 1 : 0);

    const int am0 = tid >> 2,         aj0 = (tid & 3) * 4;
    const int am1 = (tid + 256) >> 2, aj1 = ((tid + 256) & 3) * 4;
    const float* Ap0 = A + (size_t)clampN(m0 + am0) * NN + aj0;
    const float* Ap1 = A + (size_t)clampN(m0 + am1) * NN + aj1;

    const uint32_t aDst0 = (uint32_t)__cvta_generic_to_shared(&As[0][am0][aj0]);
    const uint32_t aDst1 = (uint32_t)__cvta_generic_to_shared(&As[0][am1][aj1]);
    const uint32_t bDst  = (uint32_t)__cvta_generic_to_shared(&Bf[0][0]);
    const uint32_t stageA = (uint32_t)(BM * LDK * 4);
    const uint32_t stageB = 4096u;

    float acc[8][4] = {};   // [n8][reg]

    // prologue: load chunks cBeg..cBeg+2 into stages 0..2
    #pragma unroll
    for (int p = 0; p < STAGES - 1; ++p) {
        if (p < nCh) {
            const size_t kf = (size_t)(cBeg + p) * BK;
            cp16(aDst0 + (uint32_t)p * stageA, Ap0 + kf);
            cp16(aDst1 + (uint32_t)p * stageA, Ap1 + kf);
            cp16(bDst + (uint32_t)p * stageB + (uint32_t)tid * 16,
                 &g_wbf[(size_t)(cBeg + p) * 256 + tid]);
        }
        asm volatile("cp.async.commit_group;");   // commit even if empty (keeps count)
    }

    for (int i = 0; i < nCh; ++i) {
        const int s   = i & (STAGES - 1);
        const int rem = nCh - 1 - i;               // committed groups after chunk i
        if (rem >= 2)      asm volatile("cp.async.wait_group 2;");
        else if (rem == 1) asm volatile("cp.async.wait_group 1;");
        else               asm volatile("cp.async.wait_group 0;");
        __syncthreads();   // chunk i visible to all; all warps done with iter i-1

        if (i + STAGES - 1 < nCh) {
            const int ns = (i + STAGES - 1) & (STAGES - 1);
            const size_t kf = (size_t)(cBeg + i + STAGES - 1) * BK;
            cp16(aDst0 + (uint32_t)ns * stageA, Ap0 + kf);
            cp16(aDst1 + (uint32_t)ns * stageA, Ap1 + kf);
            cp16(bDst + (uint32_t)ns * stageB + (uint32_t)tid * 16,
                 &g_wbf[(size_t)(cBeg + i + STAGES - 1) * 256 + tid]);
            asm volatile("cp.async.commit_group;");
        }

        uint4 bv[8];
        #pragma unroll
        for (int n8 = 0; n8 < 8; ++n8)
            bv[n8] = Bf[s][n8 * 32 + lane];

        const int r0 = wid * 16 + g;
        const float2 p0 = *reinterpret_cast<const float2*>(&As[s][r0][2 * t]);
        const float2 p1 = *reinterpret_cast<const float2*>(&As[s][r0 + 8][2 * t]);
        const float2 p2 = *reinterpret_cast<const float2*>(&As[s][r0][2 * t + 8]);
        const float2 p3 = *reinterpret_cast<const float2*>(&As[s][r0 + 8][2 * t + 8]);
        uint32_t ah[4], al[4];
        bfsplit2(p0.x, p0.y, ah[0], al[0]);
        bfsplit2(p1.x, p1.y, ah[1], al[1]);
        bfsplit2(p2.x, p2.y, ah[2], al[2]);
        bfsplit2(p3.x, p3.y, ah[3], al[3]);

        #pragma unroll
        for (int n8 = 0; n8 < 8; ++n8)
            mma16(acc[n8], ah, bv[n8].x, bv[n8].y);   // hi*hi
        #pragma unroll
        for (int n8 = 0; n8 < 8; ++n8)
            mma16(acc[n8], ah, bv[n8].z, bv[n8].w);   // hi*lo
        #pragma unroll
        for (int n8 = 0; n8 < 8; ++n8)
            mma16(acc[n8], al, bv[n8].x, bv[n8].y);   // lo*hi
    }

    float* outp = &g_part[(size_t)part * NN * F1];
    const int r0g = m0 + wid * 16 + g;
    const int r1g = r0g + 8;
    #pragma unroll
    for (int n8 = 0; n8 < 8; ++n8) {
        const int col = n8 * 8 + 2 * t;
        if (r0g < NN) {
            float2 v0 = make_float2(acc[n8][0], acc[n8][1]);
            *reinterpret_cast<float2*>(&outp[(size_t)r0g * F1 + col]) = v0;
        }
        if (r1g < NN) {
            float2 v1 = make_float2(acc[n8][2], acc[n8][3]);
            *reinterpret_cast<float2*>(&outp[(size_t)r1g * F1 + col]) = v1;
        }
    }
}

// reduce split-K partials -> g_bufA
__global__ void reduce_part_kernel() {
    int idx4 = blockIdx.x * blockDim.x + threadIdx.x;
    if (idx4 < NN * F1 / 4) {
        float4 s = make_float4(0.f, 0.f, 0.f, 0.f);
        #pragma unroll
        for (int p = 0; p < SPLIT; ++p) {
            const float4 v = *reinterpret_cast<const float4*>(
                &g_part[(size_t)p * NN * F1 + (size_t)idx4 * 4]);
            s.x += v.x; s.y += v.y; s.z += v.z; s.w += v.w;
        }
        *reinterpret_cast<float4*>(&g_bufA[(size_t)idx4 * 4]) = s;
    }
}

// ---- small GEMMs: g_bufB [NN,64] x W [64,C] -> g_bufA --------------------
template <int CIN, int C>
__global__ void gemm_small_kernel(const float* __restrict__ W) {
    __shared__ float w_s[CIN * C];
    for (int i = threadIdx.x; i < CIN * C; i += blockDim.x) w_s[i] = W[i];
    __syncthreads();
    const int total  = NN * C;
    const int stride = gridDim.x * blockDim.x;
    for (int idx = blockIdx.x * blockDim.x + threadIdx.x; idx < total; idx += stride) {
        const int row = idx / C;
        const int col = idx % C;
        const float* rp = &g_bufB[(size_t)row * CIN];
        float acc = 0.0f;
        #pragma unroll
        for (int k = 0; k < CIN; ++k) acc += rp[k] * w_s[k * C + col];
        g_bufA[idx] = acc;
    }
}

// ---- CSR pull aggregation (+fused bias/relu) [verified r14] --------------
template <int C, bool BIAS_RELU>
__global__ void agg_csr_kernel(const float* __restrict__ bias) {
    const int w    = (blockIdx.x * blockDim.x + threadIdx.x) >> 5;
    const int lane = threadIdx.x & 31;
    if (w >= NN) return;
    constexpr int L = C / 2;
    const int dst = w;
    const float dd = g_dinv[dst];
    const int p0 = g_ptr[dst];
    const int p1 = g_ptr[dst + 1];

    float2 acc = make_float2(0.f, 0.f);
    if (lane < L) {
        const float2 v = *reinterpret_cast<const float2*>(&g_bufA[(size_t)dst * C + lane * 2]);
        acc.x = v.x * dd * dd;
        acc.y = v.y * dd * dd;
    }
    int j = p0;
    for (; j + 1 < p1; j += 2) {
        const int s0 = g_csrc[j];
        const int s1 = g_csrc[j + 1];
        const float n0 = g_dinv[s0] * dd;
        const float n1 = g_dinv[s1] * dd;
        if (lane < L) {
            const float2 v0 = *reinterpret_cast<const float2*>(&g_bufA[(size_t)s0 * C + lane * 2]);
            const float2 v1 = *reinterpret_cast<const float2*>(&g_bufA[(size_t)s1 * C + lane * 2]);
            acc.x += v0.x * n0; acc.y += v0.y * n0;
            acc.x += v1.x * n1; acc.y += v1.y * n1;
        }
    }
    if (j < p1) {
        const int s0 = g_csrc[j];
        const float n0 = g_dinv[s0] * dd;
        if (lane < L) {
            const float2 v0 = *reinterpret_cast<const float2*>(&g_bufA[(size_t)s0 * C + lane * 2]);
            acc.x += v0.x * n0; acc.y += v0.y * n0;
        }
    }
    if (lane < L) {
        if (BIAS_RELU) {
            const float2 bb = *reinterpret_cast<const float2*>(&bias[lane * 2]);
            acc.x = fmaxf(acc.x + bb.x, 0.f);
            acc.y = fmaxf(acc.y + bb.y, 0.f);
        }
        *reinterpret_cast<float2*>(&g_bufB[(size_t)dst * C + lane * 2]) = acc;
    }
}

// ---------------- softmax (adds bias b3) ----------------
__global__ void softmax_kernel(const float* __restrict__ b, float* __restrict__ out) {
    int r = blockIdx.x * blockDim.x + threadIdx.x;
    if (r >= NN) return;
    float v[COUT];
    float m = -1e30f;
    #pragma unroll
    for (int j = 0; j < COUT; ++j) {
        v[j] = g_bufB[(size_t)r * COUT + j] + b[j];
        m = fmaxf(m, v[j]);
    }
    float s = 0.0f;
    #pragma unroll
    for (int j = 0; j < COUT; ++j) {
        v[j] = expf(v[j] - m);
        s += v[j];
    }
    const float inv = 1.0f / s;
    #pragma unroll
    for (int j = 0; j < COUT; ++j) out[(size_t)r * COUT + j] = v[j] * inv;
}

// ---------------- launch ----------------
extern "C" void kernel_launch(void* const* d_in, const int* in_sizes, int n_in,
                              void* d_out, int out_size) {
    const float* x  = (const float*)d_in[0];
    const int*   ei = (const int*)d_in[1];   // int32 (JAX x64 disabled)
    const float* W1 = (const float*)d_in[2];
    const float* b1 = (const float*)d_in[3];
    const float* W2 = (const float*)d_in[4];
    const float* b2 = (const float*)d_in[5];
    const float* W3 = (const float*)d_in[6];
    const float* b3 = (const float*)d_in[7];
    float* out = (float*)d_out;

    int E = in_sizes[1] / 2;
    if (E > E_MAX) E = E_MAX;

    const int T = 256;
    const int gN    = (NN + T - 1) / T;
    const int gE    = (E + T - 1) / T;
    const int g64v  = (NN * F1 / 4 + T - 1) / T;
    const int gWarp = (NN * 32 + T - 1) / T;
    const dim3 gG((NN + BM - 1) / BM, SPLIT);   // 79 x 16

    // degree + CSR + norm + W1 prep
    deg_init_kernel<<<gN, T>>>();
    deg_count_kernel<<<gE, T>>>(ei, E);
    dinv_kernel<<<gN, T>>>();
    csr_scan_kernel<<<1, 1024>>>();
    csr_scatter_kernel<<<gE, T>>>(ei, E);
    wfrag_kernel<<<(NCH * 256 + T - 1) / T, T>>>(W1);

    // ---- layer 1 ----
    gemm1_mma_kernel<<<gG, 256>>>(x);
    reduce_part_kernel<<<g64v, T>>>();
    agg_csr_kernel<F1, true><<<gWarp, T>>>(b1);

    // ---- layer 2 ----
    gemm_small_kernel<F1, F1><<<1480, T>>>(W2);
    agg_csr_kernel<F1, true><<<gWarp, T>>>(b2);

    // ---- layer 3 ----
    gemm_small_kernel<F1, COUT><<<1480, T>>>(W3);
    agg_csr_kernel<COUT, false><<<gWarp, T>>>(nullptr);
    softmax_kernel<<<gN, T>>>(b3, out);
}